// round 4
// baseline (speedup 1.0000x reference)
#include <cuda_runtime.h>
#include <cstdint>

#define B_ 8
#define T_ 4096
#define D_ 512
#define H_ 512
#define M_ (B_*T_)      // 32768 rows
#define NC 64
#define LC (T_/NC)      // 64

// ----------------------------- scratch (device globals) -----------------------------
__device__ float g_Xp[(size_t)M_*D_];   // [M/16][D/8][128]  (16m x 8k blocks, fragment order)
__device__ float g_Wp[1024*512];        // [N/8][D/8][64]    (8n x 8k blocks, fused [Wz;Wh])
__device__ float g_C[(size_t)M_*H_];    // c_t = sigmoid(-k)
__device__ float g_G[(size_t)M_*H_];    // g(pre_h)
__device__ float g_A[B_*NC*H_];
__device__ float g_S[B_*NC*H_];
__device__ float g_Hb[B_*NC*H_];

__device__ __forceinline__ float sigmoidf_(float x) { return 1.0f / (1.0f + __expf(-x)); }

__device__ __forceinline__ float f2tf32f(float f) {
    uint32_t u;
    asm volatile("cvt.rna.tf32.f32 %0, %1;" : "=r"(u) : "f"(f));
    return __uint_as_float(u);
}

__device__ __forceinline__ void mma_tf32(float d[4], const uint32_t a[4], const uint32_t b[2]) {
    asm volatile(
        "mma.sync.aligned.m16n8k8.row.col.f32.tf32.tf32.f32 "
        "{%0,%1,%2,%3}, {%4,%5,%6,%7}, {%8,%9}, {%0,%1,%2,%3};\n"
        : "+f"(d[0]), "+f"(d[1]), "+f"(d[2]), "+f"(d[3])
        : "r"(a[0]), "r"(a[1]), "r"(a[2]), "r"(a[3]), "r"(b[0]), "r"(b[1]));
}

#define CP_ASYNC16(sa, gp) asm volatile("cp.async.cg.shared.global [%0], [%1], 16;" :: "r"(sa), "l"(__cvta_generic_to_global(gp)) : "memory")
#define CP_COMMIT()        asm volatile("cp.async.commit_group;" ::: "memory")
#define CP_WAIT2()         asm volatile("cp.async.wait_group 2;" ::: "memory")

__device__ __forceinline__ uint32_t smem_u32(const void* p) {
    uint32_t a;
    asm("{ .reg .u64 t; cvta.to.shared.u64 t, %1; cvt.u32.u64 %0, t; }" : "=r"(a) : "l"(p));
    return a;
}

// ----------------------------- prep: tf32-round + fragment pack -----------------------------
#define XBLOCKS ((M_/16)*(D_/8))     // 131072
#define WBLOCKS ((1024/8)*(D_/8))    // 8192

__global__ __launch_bounds__(256) void prep_kernel(
    const float* __restrict__ x, const float* __restrict__ Wz, const float* __restrict__ Wh)
{
    const int gw   = blockIdx.x * 8 + (threadIdx.x >> 5);
    const int lane = threadIdx.x & 31;
    const int r = lane >> 2, c = lane & 3;

    if (gw < XBLOCKS) {
        const int mb = gw >> 6;
        const int kb = gw & 63;
        const float* xp = x + (size_t)(mb * 16) * D_ + kb * 8;
        float4 v;
        v.x = f2tf32f(xp[(size_t)r * D_ + c]);
        v.y = f2tf32f(xp[(size_t)(r + 8) * D_ + c]);
        v.z = f2tf32f(xp[(size_t)r * D_ + c + 4]);
        v.w = f2tf32f(xp[(size_t)(r + 8) * D_ + c + 4]);
        reinterpret_cast<float4*>(g_Xp)[(size_t)gw * 32 + lane] = v;
    } else {
        const int wb = gw - XBLOCKS;
        const int nb = wb >> 6;
        const int kb = wb & 63;
        const int n = nb * 8 + r;
        const float* Wrow = (n < 512) ? (Wz + (size_t)n * D_) : (Wh + (size_t)(n - 512) * D_);
        float2 v;
        v.x = f2tf32f(Wrow[kb * 8 + c]);
        v.y = f2tf32f(Wrow[kb * 8 + c + 4]);
        reinterpret_cast<float2*>(g_Wp)[(size_t)wb * 32 + lane] = v;
    }
}

// ----------------------------- GEMM + activation (mma.sync tf32, cp.async pipe) ---------------
// CTA tile: 256m x 128n; warp tile 64m x 64n (wm 0..3, wn 0..1); K staged 16 (32 stages), 4 bufs.
#define KSTAGES 32
#define NBUF 4
#define A_STAGE_BYTES 16384     // 16 mblocks x 2 kblocks x 512B
#define B_STAGE_BYTES 8192      // 16 nblocks x 2 kblocks x 256B
#define STAGE_BYTES (A_STAGE_BYTES + B_STAGE_BYTES)
#define GEMM_SMEM (NBUF*STAGE_BYTES + 1024)   // 99328

__global__ __launch_bounds__(256, 1) void gemm_act_kernel(
    const float* __restrict__ bz, const float* __restrict__ bh)
{
    extern __shared__ char dyn[];
    float* sBias = reinterpret_cast<float*>(dyn + NBUF * STAGE_BYTES);
    const uint32_t sbase = smem_u32(dyn);

    const int tid  = threadIdx.x;
    const int wid  = tid >> 5;
    const int lane = tid & 31;
    const int wm = wid >> 1;     // 0..3  (64 rows each)
    const int wn = wid & 1;      // 0..1  (64 cols each)

    const int bn = blockIdx.x;   // 0..7 over fused N=1024
    const int bm = blockIdx.y;   // 0..127 (256 rows each)
    const bool isZ = (bn < 4);
    const int nbase = (bn & 3) * 128;
    const int m0 = bm * 256;
    const int mb0 = bm * 16;
    const int nb0 = bn * 16;

    if (tid < 128) sBias[tid] = isZ ? bz[nbase + tid] : bh[nbase + tid];

    float acc[4][8][4];
    #pragma unroll
    for (int i = 0; i < 4; i++)
        #pragma unroll
        for (int j = 0; j < 8; j++)
            #pragma unroll
            for (int q = 0; q < 4; q++) acc[i][j][q] = 0.f;

    auto load_stage = [&](int s, int buf) {
        const int kb0 = s * 2;
        const uint32_t stA = sbase + buf * STAGE_BYTES;
        const uint32_t stB = stA + A_STAGE_BYTES;
        #pragma unroll
        for (int i = 0; i < 4; i++) {            // A: 1024 segs of 16B
            const int seg = tid + i * 256;
            const int mbi = seg >> 6;
            const int w   = seg & 63;
            const float* gp = g_Xp + ((size_t)(mb0 + mbi) * 64 + kb0) * 128 + w * 4;
            CP_ASYNC16(stA + seg * 16, gp);
        }
        #pragma unroll
        for (int i = 0; i < 2; i++) {            // B: 512 segs of 16B
            const int seg = tid + i * 256;
            const int nbi = seg >> 5;
            const int w   = seg & 31;
            const float* gp = g_Wp + ((size_t)(nb0 + nbi) * 64 + kb0) * 64 + w * 4;
            CP_ASYNC16(stB + seg * 16, gp);
        }
    };

    load_stage(0, 0); CP_COMMIT();
    load_stage(1, 1); CP_COMMIT();
    load_stage(2, 2); CP_COMMIT();

    for (int s = 0; s < KSTAGES; s++) {
        CP_WAIT2();
        __syncthreads();
        if (s + 3 < KSTAGES) load_stage(s + 3, (s + 3) & 3);
        CP_COMMIT();

        const char* stA = dyn + ((s & 3) * STAGE_BYTES);
        const char* stB = stA + A_STAGE_BYTES;

        #pragma unroll
        for (int ks = 0; ks < 2; ks++) {
            uint32_t af[4][4];
            uint32_t bf[8][2];
            #pragma unroll
            for (int mt = 0; mt < 4; mt++) {
                const int mb = wm * 4 + mt;
                const uint4 v = *reinterpret_cast<const uint4*>(stA + (mb * 2 + ks) * 512 + lane * 16);
                af[mt][0] = v.x; af[mt][1] = v.y; af[mt][2] = v.z; af[mt][3] = v.w;
            }
            #pragma unroll
            for (int nt = 0; nt < 8; nt++) {
                const int nb = wn * 8 + nt;
                const uint2 v = *reinterpret_cast<const uint2*>(stB + (nb * 2 + ks) * 256 + lane * 8);
                bf[nt][0] = v.x; bf[nt][1] = v.y;
            }
            #pragma unroll
            for (int mt = 0; mt < 4; mt++)
                #pragma unroll
                for (int nt = 0; nt < 8; nt++)
                    mma_tf32(acc[mt][nt], af[mt], bf[nt]);
        }
    }

    // ---- epilogue: bias + activation ----
    float* __restrict__ outBuf = isZ ? g_C : g_G;
    const int row0 = m0 + wm * 64 + (lane >> 2);
    const int col0 = wn * 64 + 2 * (lane & 3);

    #pragma unroll
    for (int mt = 0; mt < 4; mt++) {
        #pragma unroll
        for (int nt = 0; nt < 8; nt++) {
            const int cl = col0 + nt * 8;
            const float b0v = sBias[cl];
            const float b1v = sBias[cl + 1];
            const int c = nbase + cl;
            #pragma unroll
            for (int half = 0; half < 2; half++) {
                const int rr = row0 + mt * 16 + half * 8;
                float v0 = acc[mt][nt][half * 2 + 0] + b0v;
                float v1 = acc[mt][nt][half * 2 + 1] + b1v;
                float o0, o1;
                if (isZ) {
                    o0 = sigmoidf_(-v0);
                    o1 = sigmoidf_(-v1);
                } else {
                    o0 = (v0 >= 0.f) ? (v0 + 0.5f) : sigmoidf_(v0);
                    o1 = (v1 >= 0.f) ? (v1 + 0.5f) : sigmoidf_(v1);
                }
                *reinterpret_cast<float2*>(&outBuf[(size_t)rr * H_ + c]) = make_float2(o0, o1);
            }
        }
    }
}

// ----------------------------- scan phase A: per-chunk reduce -----------------------------
__global__ __launch_bounds__(256) void scan_phaseA()
{
    const int idx = blockIdx.x * 256 + threadIdx.x;     // 0 .. 65535
    const int h4 = idx & 127;
    const int ch = (idx >> 7) & (NC - 1);
    const int b  = idx >> 13;
    const float4* C4 = reinterpret_cast<const float4*>(g_C);
    const float4* G4 = reinterpret_cast<const float4*>(g_G);
    size_t p = ((size_t)(b * T_ + ch * LC) * H_) / 4 + h4;

    float4 A = make_float4(1.f,1.f,1.f,1.f);
    float4 s = make_float4(0.f,0.f,0.f,0.f);
    #pragma unroll 4
    for (int t = 0; t < LC; t++, p += H_/4) {
        const float4 c = C4[p];
        const float4 g = G4[p];
        s.x = c.x*s.x + (1.f-c.x)*g.x;  A.x *= c.x;
        s.y = c.y*s.y + (1.f-c.y)*g.y;  A.y *= c.y;
        s.z = c.z*s.z + (1.f-c.z)*g.z;  A.z *= c.z;
        s.w = c.w*s.w + (1.f-c.w)*g.w;  A.w *= c.w;
    }
    reinterpret_cast<float4*>(g_A)[idx] = A;
    reinterpret_cast<float4*>(g_S)[idx] = s;
}

// ----------------------------- scan phase B: warp-parallel chunk combine ----------------------
// One warp per (b, h-quad). Lane l covers chunks 2l, 2l+1. Composition scan via shfl.
__global__ __launch_bounds__(256) void scan_phaseB(const float* __restrict__ h0)
{
    const int q    = blockIdx.x * 8 + (threadIdx.x >> 5);   // 0..1023
    const int lane = threadIdx.x & 31;
    const int b  = q >> 7;
    const int h4 = q & 127;

    const float4* A4 = reinterpret_cast<const float4*>(g_A);
    const float4* S4 = reinterpret_cast<const float4*>(g_S);
    float4* Hb4 = reinterpret_cast<float4*>(g_Hb);

    const int o0 = (b * NC + 2 * lane) * 128 + h4;
    const int o1 = o0 + 128;
    const float4 A0 = A4[o0], S0 = S4[o0];
    const float4 A1 = A4[o1], S1 = S4[o1];

    // compose the lane's 2 chunks (apply c0 then c1)
    float4 Ap, Sp;
    Ap.x = A0.x*A1.x;  Sp.x = A1.x*S0.x + S1.x;
    Ap.y = A0.y*A1.y;  Sp.y = A1.y*S0.y + S1.y;
    Ap.z = A0.z*A1.z;  Sp.z = A1.z*S0.z + S1.z;
    Ap.w = A0.w*A1.w;  Sp.w = A1.w*S0.w + S1.w;

    // inclusive warp scan (prev ∘ cur): A = Ap_prev*Ap, S = Ap*S_prev + Sp
    #pragma unroll
    for (int d = 1; d < 32; d <<= 1) {
        float4 Au, Su;
        Au.x = __shfl_up_sync(0xFFFFFFFFu, Ap.x, d);
        Au.y = __shfl_up_sync(0xFFFFFFFFu, Ap.y, d);
        Au.z = __shfl_up_sync(0xFFFFFFFFu, Ap.z, d);
        Au.w = __shfl_up_sync(0xFFFFFFFFu, Ap.w, d);
        Su.x = __shfl_up_sync(0xFFFFFFFFu, Sp.x, d);
        Su.y = __shfl_up_sync(0xFFFFFFFFu, Sp.y, d);
        Su.z = __shfl_up_sync(0xFFFFFFFFu, Sp.z, d);
        Su.w = __shfl_up_sync(0xFFFFFFFFu, Sp.w, d);
        if (lane >= d) {
            Sp.x = Ap.x*Su.x + Sp.x;  Ap.x *= Au.x;
            Sp.y = Ap.y*Su.y + Sp.y;  Ap.y *= Au.y;
            Sp.z = Ap.z*Su.z + Sp.z;  Ap.z *= Au.z;
            Sp.w = Ap.w*Su.w + Sp.w;  Ap.w *= Au.w;
        }
    }

    // exclusive prefix
    float4 Ae, Se;
    Ae.x = __shfl_up_sync(0xFFFFFFFFu, Ap.x, 1);
    Ae.y = __shfl_up_sync(0xFFFFFFFFu, Ap.y, 1);
    Ae.z = __shfl_up_sync(0xFFFFFFFFu, Ap.z, 1);
    Ae.w = __shfl_up_sync(0xFFFFFFFFu, Ap.w, 1);
    Se.x = __shfl_up_sync(0xFFFFFFFFu, Sp.x, 1);
    Se.y = __shfl_up_sync(0xFFFFFFFFu, Sp.y, 1);
    Se.z = __shfl_up_sync(0xFFFFFFFFu, Sp.z, 1);
    Se.w = __shfl_up_sync(0xFFFFFFFFu, Sp.w, 1);
    if (lane == 0) {
        Ae = make_float4(1.f,1.f,1.f,1.f);
        Se = make_float4(0.f,0.f,0.f,0.f);
    }

    // initial state g(h0)
    const float4 v = reinterpret_cast<const float4*>(h0)[b * 128 + h4];
    float4 s0;
    s0.x = (v.x >= 0.f) ? (v.x + 0.5f) : sigmoidf_(v.x);
    s0.y = (v.y >= 0.f) ? (v.y + 0.5f) : sigmoidf_(v.y);
    s0.z = (v.z >= 0.f) ? (v.z + 0.5f) : sigmoidf_(v.z);
    s0.w = (v.w >= 0.f) ? (v.w + 0.5f) : sigmoidf_(v.w);

    float4 st;
    st.x = Ae.x*s0.x + Se.x;
    st.y = Ae.y*s0.y + Se.y;
    st.z = Ae.z*s0.z + Se.z;
    st.w = Ae.w*s0.w + Se.w;
    Hb4[o0] = st;

    float4 st1;
    st1.x = A0.x*st.x + S0.x;
    st1.y = A0.y*st.y + S0.y;
    st1.z = A0.z*st.z + S0.z;
    st1.w = A0.w*st.w + S0.w;
    Hb4[o1] = st1;
}

// ----------------------------- scan phase C: rescan + output -----------------------------
__global__ __launch_bounds__(256) void scan_phaseC(float* __restrict__ out)
{
    const int idx = blockIdx.x * 256 + threadIdx.x;
    const int h4 = idx & 127;
    const int ch = (idx >> 7) & (NC - 1);
    const int b  = idx >> 13;
    const float4* C4 = reinterpret_cast<const float4*>(g_C);
    const float4* G4 = reinterpret_cast<const float4*>(g_G);
    float4* O4 = reinterpret_cast<float4*>(out);
    size_t p = ((size_t)(b * T_ + ch * LC) * H_) / 4 + h4;

    float4 st = reinterpret_cast<const float4*>(g_Hb)[(b * NC + ch) * 128 + h4];
    #pragma unroll 4
    for (int t = 0; t < LC; t++, p += H_/4) {
        const float4 c = C4[p];
        const float4 g = G4[p];
        st.x = c.x*st.x + (1.f-c.x)*g.x;
        st.y = c.y*st.y + (1.f-c.y)*g.y;
        st.z = c.z*st.z + (1.f-c.z)*g.z;
        st.w = c.w*st.w + (1.f-c.w)*g.w;
        O4[p] = st;
    }
}

extern "C" void kernel_launch(void* const* d_in, const int* in_sizes, int n_in,
                              void* d_out, int out_size)
{
    const float* x  = (const float*)d_in[0];
    const float* h0 = (const float*)d_in[1];
    const float* Wz = (const float*)d_in[2];
    const float* bz = (const float*)d_in[3];
    const float* Wh = (const float*)d_in[4];
    const float* bh = (const float*)d_in[5];
    float* out = (float*)d_out;

    cudaFuncSetAttribute(gemm_act_kernel, cudaFuncAttributeMaxDynamicSharedMemorySize, GEMM_SMEM);

    prep_kernel<<<(XBLOCKS + WBLOCKS) / 8, 256>>>(x, Wz, Wh);
    gemm_act_kernel<<<dim3(8, 128), 256, GEMM_SMEM>>>(bz, bh);
    scan_phaseA<<<256, 256>>>();
    scan_phaseB<<<128, 256>>>(h0);
    scan_phaseC<<<256, 256>>>(out);
}

// round 5
// speedup vs baseline: 1.6996x; 1.6996x over previous
#include <cuda_runtime.h>
#include <cuda_fp16.h>
#include <cstdint>

#define B_ 8
#define T_ 4096
#define D_ 512
#define H_ 512
#define M_ (B_*T_)      // 32768 rows
#define NC 64
#define LC (T_/NC)      // 64

// ----------------------------- scratch (device globals) -----------------------------
// Fragment-packed fp16 operands for mma.m16n8k16
__device__ __half g_Xp[(size_t)M_*D_];  // [M/16][D/16][256]  (16m x 16k blocks)
__device__ __half g_Wp[1024*512];       // [N/8][D/16][128]   (8n x 16k blocks, fused [Wz;Wh])
__device__ float g_C[(size_t)M_*H_];    // c_t = sigmoid(-k)
__device__ float g_G[(size_t)M_*H_];    // g(pre_h)
__device__ float g_A[B_*NC*H_];
__device__ float g_S[B_*NC*H_];
__device__ float g_Hb[B_*NC*H_];

__device__ __forceinline__ float sigmoidf_(float x) { return 1.0f / (1.0f + __expf(-x)); }

__device__ __forceinline__ void mma_f16(float d[4], const uint32_t a[4], const uint32_t b[2]) {
    asm volatile(
        "mma.sync.aligned.m16n8k16.row.col.f32.f16.f16.f32 "
        "{%0,%1,%2,%3}, {%4,%5,%6,%7}, {%8,%9}, {%0,%1,%2,%3};\n"
        : "+f"(d[0]), "+f"(d[1]), "+f"(d[2]), "+f"(d[3])
        : "r"(a[0]), "r"(a[1]), "r"(a[2]), "r"(a[3]), "r"(b[0]), "r"(b[1]));
}

#define CP_ASYNC16(sa, gp) asm volatile("cp.async.cg.shared.global [%0], [%1], 16;" :: "r"(sa), "l"(__cvta_generic_to_global(gp)) : "memory")
#define CP_COMMIT()        asm volatile("cp.async.commit_group;" ::: "memory")
#define CP_WAIT2()         asm volatile("cp.async.wait_group 2;" ::: "memory")

__device__ __forceinline__ uint32_t smem_u32(const void* p) {
    uint32_t a;
    asm("{ .reg .u64 t; cvta.to.shared.u64 t, %1; cvt.u32.u64 %0, t; }" : "=r"(a) : "l"(p));
    return a;
}

__device__ __forceinline__ uint32_t pack2h(float a, float b) {
    __half2 h = __floats2half2_rn(a, b);
    return *reinterpret_cast<uint32_t*>(&h);
}

// ----------------------------- prep: f32 -> fp16 fragment pack -----------------------------
// x blocks: 16m x 16k. Lane (r=lane>>2, c=lane&3) packs the 8 halves of its mma A fragment:
//   {x[r][2c],x[r][2c+1]} {x[r+8][2c],x[r+8][2c+1]} {x[r][2c+8],x[r][2c+9]} {x[r+8][2c+8],x[r+8][2c+9]}
// W blocks: 8n x 16k. Lane (g=lane>>2, c=lane&3) packs its B fragment (B[k][n] = W[n][k]):
//   {W[g][2c],W[g][2c+1]} {W[g][2c+8],W[g][2c+9]}
#define XBLOCKS ((M_/16)*(D_/16))    // 65536
#define WBLOCKS ((1024/8)*(D_/16))   // 4096

__global__ __launch_bounds__(256) void prep_kernel(
    const float* __restrict__ x, const float* __restrict__ Wz, const float* __restrict__ Wh)
{
    const int gw   = blockIdx.x * 8 + (threadIdx.x >> 5);
    const int lane = threadIdx.x & 31;
    const int r = lane >> 2, c = lane & 3;

    if (gw < XBLOCKS) {
        const int mb = gw >> 5;          // D_/16 = 32 k-blocks per m-block row
        const int kb = gw & 31;
        const float* xp = x + (size_t)(mb * 16) * D_ + kb * 16;
        uint4 v;
        v.x = pack2h(xp[(size_t)r * D_ + 2*c],       xp[(size_t)r * D_ + 2*c + 1]);
        v.y = pack2h(xp[(size_t)(r+8) * D_ + 2*c],   xp[(size_t)(r+8) * D_ + 2*c + 1]);
        v.z = pack2h(xp[(size_t)r * D_ + 2*c + 8],   xp[(size_t)r * D_ + 2*c + 9]);
        v.w = pack2h(xp[(size_t)(r+8) * D_ + 2*c+8], xp[(size_t)(r+8) * D_ + 2*c + 9]);
        reinterpret_cast<uint4*>(g_Xp)[(size_t)gw * 32 + lane] = v;
    } else {
        const int wb = gw - XBLOCKS;     // 0..4095
        const int nb = wb >> 5;
        const int kb = wb & 31;
        const int n = nb * 8 + r;        // fused n in [0,1024)
        const float* Wrow = (n < 512) ? (Wz + (size_t)n * D_) : (Wh + (size_t)(n - 512) * D_);
        uint2 v;
        v.x = pack2h(Wrow[kb*16 + 2*c],     Wrow[kb*16 + 2*c + 1]);
        v.y = pack2h(Wrow[kb*16 + 2*c + 8], Wrow[kb*16 + 2*c + 9]);
        reinterpret_cast<uint2*>(g_Wp)[(size_t)wb * 32 + lane] = v;
    }
}

// ----------------------------- GEMM + activation (mma.sync fp16, cp.async pipe) ---------------
// CTA tile: 128m x 128n, warp tile 64m x 32n (wm 0..1, wn 0..3).
// K staged 32 at a time (16 stages), 4 smem buffers.
#define KSTAGES 16
#define NBUF 4
#define A_STAGE_BYTES 8192      // 8 mblocks x 2 kblocks x 512B
#define B_STAGE_BYTES 8192      // 16 nblocks x 2 kblocks x 256B
#define STAGE_BYTES (A_STAGE_BYTES + B_STAGE_BYTES)
#define GEMM_SMEM (NBUF*STAGE_BYTES + 1024)   // 66560

__global__ __launch_bounds__(256, 2) void gemm_act_kernel(
    const float* __restrict__ bz, const float* __restrict__ bh)
{
    extern __shared__ char dyn[];
    float* sBias = reinterpret_cast<float*>(dyn + NBUF * STAGE_BYTES);
    const uint32_t sbase = smem_u32(dyn);

    const int tid  = threadIdx.x;
    const int wid  = tid >> 5;
    const int lane = tid & 31;
    const int wm = wid >> 2;     // 0..1
    const int wn = wid & 3;      // 0..3

    const int bn = blockIdx.x;   // 0..7 over fused N=1024
    const int bm = blockIdx.y;   // 0..255
    const bool isZ = (bn < 4);
    const int nbase = (bn & 3) * 128;
    const int m0 = bm * 128;
    const int mb0 = bm * 8;      // first 16-row block
    const int nb0 = bn * 16;     // first 8-col block (fused n space)

    if (tid < 128) sBias[tid] = isZ ? bz[nbase + tid] : bh[nbase + tid];

    float acc[4][4][4];
    #pragma unroll
    for (int i = 0; i < 4; i++)
        #pragma unroll
        for (int j = 0; j < 4; j++)
            #pragma unroll
            for (int q = 0; q < 4; q++) acc[i][j][q] = 0.f;

    // ---- stage loader: 16KB per stage ----
    auto load_stage = [&](int s, int buf) {
        const int kb0 = s * 2;
        const uint32_t stA = sbase + buf * STAGE_BYTES;
        const uint32_t stB = stA + A_STAGE_BYTES;
        // A: 512 segs of 16B; per m-block: 2 k-blocks = 1KB contiguous
        #pragma unroll
        for (int i = 0; i < 2; i++) {
            const int seg = tid + i * 256;
            const int mbi = seg >> 6;
            const int w   = seg & 63;
            const __half* gp = g_Xp + ((size_t)(mb0 + mbi) * 32 + kb0) * 256 + w * 8;
            CP_ASYNC16(stA + seg * 16, gp);
        }
        // B: 512 segs of 16B; per n-block: 2 k-blocks = 512B contiguous
        #pragma unroll
        for (int i = 0; i < 2; i++) {
            const int seg = tid + i * 256;
            const int nbi = seg >> 5;
            const int w   = seg & 31;
            const __half* gp = g_Wp + ((size_t)(nb0 + nbi) * 32 + kb0) * 128 + w * 8;
            CP_ASYNC16(stB + seg * 16, gp);
        }
    };

    load_stage(0, 0); CP_COMMIT();
    load_stage(1, 1); CP_COMMIT();
    load_stage(2, 2); CP_COMMIT();

    for (int s = 0; s < KSTAGES; s++) {
        CP_WAIT2();
        __syncthreads();
        if (s + 3 < KSTAGES) load_stage(s + 3, (s + 3) & 3);
        CP_COMMIT();

        const char* stA = dyn + ((s & 3) * STAGE_BYTES);
        const char* stB = stA + A_STAGE_BYTES;

        #pragma unroll
        for (int ks = 0; ks < 2; ks++) {
            uint32_t af[4][4];
            uint32_t bf[4][2];
            #pragma unroll
            for (int mt = 0; mt < 4; mt++) {
                const int mb = wm * 4 + mt;
                const uint4 v = *reinterpret_cast<const uint4*>(stA + (mb * 2 + ks) * 512 + lane * 16);
                af[mt][0] = v.x; af[mt][1] = v.y; af[mt][2] = v.z; af[mt][3] = v.w;
            }
            #pragma unroll
            for (int nt = 0; nt < 4; nt++) {
                const int nb = wn * 4 + nt;
                const uint2 v = *reinterpret_cast<const uint2*>(stB + (nb * 2 + ks) * 256 + lane * 8);
                bf[nt][0] = v.x; bf[nt][1] = v.y;
            }
            #pragma unroll
            for (int mt = 0; mt < 4; mt++)
                #pragma unroll
                for (int nt = 0; nt < 4; nt++)
                    mma_f16(acc[mt][nt], af[mt], bf[nt]);
        }
    }

    // ---- epilogue: bias + activation ----
    float* __restrict__ outBuf = isZ ? g_C : g_G;
    const int row0 = m0 + wm * 64 + (lane >> 2);
    const int col0 = wn * 32 + 2 * (lane & 3);

    #pragma unroll
    for (int mt = 0; mt < 4; mt++) {
        #pragma unroll
        for (int nt = 0; nt < 4; nt++) {
            const int cl = col0 + nt * 8;
            const float b0v = sBias[cl];
            const float b1v = sBias[cl + 1];
            const int c = nbase + cl;
            #pragma unroll
            for (int half = 0; half < 2; half++) {
                const int rr = row0 + mt * 16 + half * 8;
                float v0 = acc[mt][nt][half * 2 + 0] + b0v;
                float v1 = acc[mt][nt][half * 2 + 1] + b1v;
                float o0, o1;
                if (isZ) {
                    o0 = sigmoidf_(-v0);
                    o1 = sigmoidf_(-v1);
                } else {
                    o0 = (v0 >= 0.f) ? (v0 + 0.5f) : sigmoidf_(v0);
                    o1 = (v1 >= 0.f) ? (v1 + 0.5f) : sigmoidf_(v1);
                }
                *reinterpret_cast<float2*>(&outBuf[(size_t)rr * H_ + c]) = make_float2(o0, o1);
            }
        }
    }
}

// ----------------------------- scan phase A: per-chunk reduce -----------------------------
__global__ __launch_bounds__(256) void scan_phaseA()
{
    const int idx = blockIdx.x * 256 + threadIdx.x;     // 0 .. 65535
    const int h4 = idx & 127;
    const int ch = (idx >> 7) & (NC - 1);
    const int b  = idx >> 13;
    const float4* C4 = reinterpret_cast<const float4*>(g_C);
    const float4* G4 = reinterpret_cast<const float4*>(g_G);
    size_t p = ((size_t)(b * T_ + ch * LC) * H_) / 4 + h4;

    float4 A = make_float4(1.f,1.f,1.f,1.f);
    float4 s = make_float4(0.f,0.f,0.f,0.f);
    #pragma unroll 4
    for (int t = 0; t < LC; t++, p += H_/4) {
        const float4 c = C4[p];
        const float4 g = G4[p];
        s.x = c.x*s.x + (1.f-c.x)*g.x;  A.x *= c.x;
        s.y = c.y*s.y + (1.f-c.y)*g.y;  A.y *= c.y;
        s.z = c.z*s.z + (1.f-c.z)*g.z;  A.z *= c.z;
        s.w = c.w*s.w + (1.f-c.w)*g.w;  A.w *= c.w;
    }
    reinterpret_cast<float4*>(g_A)[idx] = A;
    reinterpret_cast<float4*>(g_S)[idx] = s;
}

// ----------------------------- scan phase B: warp-parallel chunk combine ----------------------
__global__ __launch_bounds__(256) void scan_phaseB(const float* __restrict__ h0)
{
    const int q    = blockIdx.x * 8 + (threadIdx.x >> 5);   // 0..1023
    const int lane = threadIdx.x & 31;
    const int b  = q >> 7;
    const int h4 = q & 127;

    const float4* A4 = reinterpret_cast<const float4*>(g_A);
    const float4* S4 = reinterpret_cast<const float4*>(g_S);
    float4* Hb4 = reinterpret_cast<float4*>(g_Hb);

    const int o0 = (b * NC + 2 * lane) * 128 + h4;
    const int o1 = o0 + 128;
    const float4 A0 = A4[o0], S0 = S4[o0];
    const float4 A1 = A4[o1], S1 = S4[o1];

    float4 Ap, Sp;
    Ap.x = A0.x*A1.x;  Sp.x = A1.x*S0.x + S1.x;
    Ap.y = A0.y*A1.y;  Sp.y = A1.y*S0.y + S1.y;
    Ap.z = A0.z*A1.z;  Sp.z = A1.z*S0.z + S1.z;
    Ap.w = A0.w*A1.w;  Sp.w = A1.w*S0.w + S1.w;

    #pragma unroll
    for (int d = 1; d < 32; d <<= 1) {
        float4 Au, Su;
        Au.x = __shfl_up_sync(0xFFFFFFFFu, Ap.x, d);
        Au.y = __shfl_up_sync(0xFFFFFFFFu, Ap.y, d);
        Au.z = __shfl_up_sync(0xFFFFFFFFu, Ap.z, d);
        Au.w = __shfl_up_sync(0xFFFFFFFFu, Ap.w, d);
        Su.x = __shfl_up_sync(0xFFFFFFFFu, Sp.x, d);
        Su.y = __shfl_up_sync(0xFFFFFFFFu, Sp.y, d);
        Su.z = __shfl_up_sync(0xFFFFFFFFu, Sp.z, d);
        Su.w = __shfl_up_sync(0xFFFFFFFFu, Sp.w, d);
        if (lane >= d) {
            Sp.x = Ap.x*Su.x + Sp.x;  Ap.x *= Au.x;
            Sp.y = Ap.y*Su.y + Sp.y;  Ap.y *= Au.y;
            Sp.z = Ap.z*Su.z + Sp.z;  Ap.z *= Au.z;
            Sp.w = Ap.w*Su.w + Sp.w;  Ap.w *= Au.w;
        }
    }

    float4 Ae, Se;
    Ae.x = __shfl_up_sync(0xFFFFFFFFu, Ap.x, 1);
    Ae.y = __shfl_up_sync(0xFFFFFFFFu, Ap.y, 1);
    Ae.z = __shfl_up_sync(0xFFFFFFFFu, Ap.z, 1);
    Ae.w = __shfl_up_sync(0xFFFFFFFFu, Ap.w, 1);
    Se.x = __shfl_up_sync(0xFFFFFFFFu, Sp.x, 1);
    Se.y = __shfl_up_sync(0xFFFFFFFFu, Sp.y, 1);
    Se.z = __shfl_up_sync(0xFFFFFFFFu, Sp.z, 1);
    Se.w = __shfl_up_sync(0xFFFFFFFFu, Sp.w, 1);
    if (lane == 0) {
        Ae = make_float4(1.f,1.f,1.f,1.f);
        Se = make_float4(0.f,0.f,0.f,0.f);
    }

    const float4 v = reinterpret_cast<const float4*>(h0)[b * 128 + h4];
    float4 s0;
    s0.x = (v.x >= 0.f) ? (v.x + 0.5f) : sigmoidf_(v.x);
    s0.y = (v.y >= 0.f) ? (v.y + 0.5f) : sigmoidf_(v.y);
    s0.z = (v.z >= 0.f) ? (v.z + 0.5f) : sigmoidf_(v.z);
    s0.w = (v.w >= 0.f) ? (v.w + 0.5f) : sigmoidf_(v.w);

    float4 st;
    st.x = Ae.x*s0.x + Se.x;
    st.y = Ae.y*s0.y + Se.y;
    st.z = Ae.z*s0.z + Se.z;
    st.w = Ae.w*s0.w + Se.w;
    Hb4[o0] = st;

    float4 st1;
    st1.x = A0.x*st.x + S0.x;
    st1.y = A0.y*st.y + S0.y;
    st1.z = A0.z*st.z + S0.z;
    st1.w = A0.w*st.w + S0.w;
    Hb4[o1] = st1;
}

// ----------------------------- scan phase C: rescan + output -----------------------------
__global__ __launch_bounds__(256) void scan_phaseC(float* __restrict__ out)
{
    const int idx = blockIdx.x * 256 + threadIdx.x;
    const int h4 = idx & 127;
    const int ch = (idx >> 7) & (NC - 1);
    const int b  = idx >> 13;
    const float4* C4 = reinterpret_cast<const float4*>(g_C);
    const float4* G4 = reinterpret_cast<const float4*>(g_G);
    float4* O4 = reinterpret_cast<float4*>(out);
    size_t p = ((size_t)(b * T_ + ch * LC) * H_) / 4 + h4;

    float4 st = reinterpret_cast<const float4*>(g_Hb)[(b * NC + ch) * 128 + h4];
    #pragma unroll 4
    for (int t = 0; t < LC; t++, p += H_/4) {
        const float4 c = C4[p];
        const float4 g = G4[p];
        st.x = c.x*st.x + (1.f-c.x)*g.x;
        st.y = c.y*st.y + (1.f-c.y)*g.y;
        st.z = c.z*st.z + (1.f-c.z)*g.z;
        st.w = c.w*st.w + (1.f-c.w)*g.w;
        O4[p] = st;
    }
}

extern "C" void kernel_launch(void* const* d_in, const int* in_sizes, int n_in,
                              void* d_out, int out_size)
{
    const float* x  = (const float*)d_in[0];
    const float* h0 = (const float*)d_in[1];
    const float* Wz = (const float*)d_in[2];
    const float* bz = (const float*)d_in[3];
    const float* Wh = (const float*)d_in[4];
    const float* bh = (const float*)d_in[5];
    float* out = (float*)d_out;

    cudaFuncSetAttribute(gemm_act_kernel, cudaFuncAttributeMaxDynamicSharedMemorySize, GEMM_SMEM);

    prep_kernel<<<(XBLOCKS + WBLOCKS) / 8, 256>>>(x, Wz, Wh);
    gemm_act_kernel<<<dim3(8, 256), 256, GEMM_SMEM>>>(bz, bh);
    scan_phaseA<<<256, 256>>>();
    scan_phaseB<<<128, 256>>>(h0);
    scan_phaseC<<<256, 256>>>(out);
}

// round 6
// speedup vs baseline: 1.9308x; 1.1360x over previous
#include <cuda_runtime.h>
#include <cuda_fp16.h>
#include <cstdint>

#define B_ 8
#define T_ 4096
#define D_ 512
#define H_ 512
#define M_ (B_*T_)      // 32768 rows
#define NC 64
#define LC (T_/NC)      // 64

// ----------------------------- scratch (device globals) -----------------------------
__device__ __half g_Xp[(size_t)M_*D_];  // [M/16][D/16][256]  (16m x 16k blocks, fragment order)
__device__ __half g_Wp[1024*512];       // [N/8][D/16][128]   (8n x 16k blocks, fused [Wz;Wh])
__device__ __half g_C[(size_t)M_*H_];   // c_t = sigmoid(-k)   (fp16)
__device__ __half g_G[(size_t)M_*H_];   // g(pre_h)            (fp16)
__device__ float g_A[B_*NC*H_];
__device__ float g_S[B_*NC*H_];
__device__ float g_Hb[B_*NC*H_];

__device__ __forceinline__ float sigmoidf_(float x) { return 1.0f / (1.0f + __expf(-x)); }

__device__ __forceinline__ void mma_f16(float d[4], const uint32_t a[4], const uint32_t b[2]) {
    asm volatile(
        "mma.sync.aligned.m16n8k16.row.col.f32.f16.f16.f32 "
        "{%0,%1,%2,%3}, {%4,%5,%6,%7}, {%8,%9}, {%0,%1,%2,%3};\n"
        : "+f"(d[0]), "+f"(d[1]), "+f"(d[2]), "+f"(d[3])
        : "r"(a[0]), "r"(a[1]), "r"(a[2]), "r"(a[3]), "r"(b[0]), "r"(b[1]));
}

#define CP_ASYNC16(sa, gp) asm volatile("cp.async.cg.shared.global [%0], [%1], 16;" :: "r"(sa), "l"(__cvta_generic_to_global(gp)) : "memory")
#define CP_COMMIT()        asm volatile("cp.async.commit_group;" ::: "memory")
#define CP_WAIT2()         asm volatile("cp.async.wait_group 2;" ::: "memory")

__device__ __forceinline__ uint32_t smem_u32(const void* p) {
    uint32_t a;
    asm("{ .reg .u64 t; cvta.to.shared.u64 t, %1; cvt.u32.u64 %0, t; }" : "=r"(a) : "l"(p));
    return a;
}

__device__ __forceinline__ uint32_t pack2h(float a, float b) {
    __half2 h = __floats2half2_rn(a, b);
    return *reinterpret_cast<uint32_t*>(&h);
}

// ----------------------------- prep: f32 -> fp16 fragment pack -----------------------------
#define XBLOCKS ((M_/16)*(D_/16))    // 65536
#define WBLOCKS ((1024/8)*(D_/16))   // 4096

__global__ __launch_bounds__(256) void prep_kernel(
    const float* __restrict__ x, const float* __restrict__ Wz, const float* __restrict__ Wh)
{
    const int gw   = blockIdx.x * 8 + (threadIdx.x >> 5);
    const int lane = threadIdx.x & 31;
    const int r = lane >> 2, c = lane & 3;

    if (gw < XBLOCKS) {
        const int mb = gw >> 5;
        const int kb = gw & 31;
        const float* xp = x + (size_t)(mb * 16) * D_ + kb * 16;
        uint4 v;
        v.x = pack2h(xp[(size_t)r * D_ + 2*c],       xp[(size_t)r * D_ + 2*c + 1]);
        v.y = pack2h(xp[(size_t)(r+8) * D_ + 2*c],   xp[(size_t)(r+8) * D_ + 2*c + 1]);
        v.z = pack2h(xp[(size_t)r * D_ + 2*c + 8],   xp[(size_t)r * D_ + 2*c + 9]);
        v.w = pack2h(xp[(size_t)(r+8) * D_ + 2*c+8], xp[(size_t)(r+8) * D_ + 2*c + 9]);
        reinterpret_cast<uint4*>(g_Xp)[(size_t)gw * 32 + lane] = v;
    } else {
        const int wb = gw - XBLOCKS;
        const int nb = wb >> 5;
        const int kb = wb & 31;
        const int n = nb * 8 + r;
        const float* Wrow = (n < 512) ? (Wz + (size_t)n * D_) : (Wh + (size_t)(n - 512) * D_);
        uint2 v;
        v.x = pack2h(Wrow[kb*16 + 2*c],     Wrow[kb*16 + 2*c + 1]);
        v.y = pack2h(Wrow[kb*16 + 2*c + 8], Wrow[kb*16 + 2*c + 9]);
        reinterpret_cast<uint2*>(g_Wp)[(size_t)wb * 32 + lane] = v;
    }
}

// ----------------------------- GEMM + activation (mma.sync fp16, cp.async pipe) ---------------
#define KSTAGES 16
#define NBUF 4
#define A_STAGE_BYTES 8192
#define B_STAGE_BYTES 8192
#define STAGE_BYTES (A_STAGE_BYTES + B_STAGE_BYTES)
#define GEMM_SMEM (NBUF*STAGE_BYTES + 1024)   // 66560

__global__ __launch_bounds__(256, 2) void gemm_act_kernel(
    const float* __restrict__ bz, const float* __restrict__ bh)
{
    extern __shared__ char dyn[];
    float* sBias = reinterpret_cast<float*>(dyn + NBUF * STAGE_BYTES);
    const uint32_t sbase = smem_u32(dyn);

    const int tid  = threadIdx.x;
    const int wid  = tid >> 5;
    const int lane = tid & 31;
    const int wm = wid >> 2;
    const int wn = wid & 3;

    const int bn = blockIdx.x;
    const int bm = blockIdx.y;
    const bool isZ = (bn < 4);
    const int nbase = (bn & 3) * 128;
    const int m0 = bm * 128;
    const int mb0 = bm * 8;
    const int nb0 = bn * 16;

    if (tid < 128) sBias[tid] = isZ ? bz[nbase + tid] : bh[nbase + tid];

    float acc[4][4][4];
    #pragma unroll
    for (int i = 0; i < 4; i++)
        #pragma unroll
        for (int j = 0; j < 4; j++)
            #pragma unroll
            for (int q = 0; q < 4; q++) acc[i][j][q] = 0.f;

    auto load_stage = [&](int s, int buf) {
        const int kb0 = s * 2;
        const uint32_t stA = sbase + buf * STAGE_BYTES;
        const uint32_t stB = stA + A_STAGE_BYTES;
        #pragma unroll
        for (int i = 0; i < 2; i++) {
            const int seg = tid + i * 256;
            const int mbi = seg >> 6;
            const int w   = seg & 63;
            const __half* gp = g_Xp + ((size_t)(mb0 + mbi) * 32 + kb0) * 256 + w * 8;
            CP_ASYNC16(stA + seg * 16, gp);
        }
        #pragma unroll
        for (int i = 0; i < 2; i++) {
            const int seg = tid + i * 256;
            const int nbi = seg >> 5;
            const int w   = seg & 31;
            const __half* gp = g_Wp + ((size_t)(nb0 + nbi) * 32 + kb0) * 128 + w * 8;
            CP_ASYNC16(stB + seg * 16, gp);
        }
    };

    load_stage(0, 0); CP_COMMIT();
    load_stage(1, 1); CP_COMMIT();
    load_stage(2, 2); CP_COMMIT();

    for (int s = 0; s < KSTAGES; s++) {
        CP_WAIT2();
        __syncthreads();
        if (s + 3 < KSTAGES) load_stage(s + 3, (s + 3) & 3);
        CP_COMMIT();

        const char* stA = dyn + ((s & 3) * STAGE_BYTES);
        const char* stB = stA + A_STAGE_BYTES;

        #pragma unroll
        for (int ks = 0; ks < 2; ks++) {
            uint32_t af[4][4];
            uint32_t bf[4][2];
            #pragma unroll
            for (int mt = 0; mt < 4; mt++) {
                const int mb = wm * 4 + mt;
                const uint4 v = *reinterpret_cast<const uint4*>(stA + (mb * 2 + ks) * 512 + lane * 16);
                af[mt][0] = v.x; af[mt][1] = v.y; af[mt][2] = v.z; af[mt][3] = v.w;
            }
            #pragma unroll
            for (int nt = 0; nt < 4; nt++) {
                const int nb = wn * 4 + nt;
                const uint2 v = *reinterpret_cast<const uint2*>(stB + (nb * 2 + ks) * 256 + lane * 8);
                bf[nt][0] = v.x; bf[nt][1] = v.y;
            }
            #pragma unroll
            for (int mt = 0; mt < 4; mt++)
                #pragma unroll
                for (int nt = 0; nt < 4; nt++)
                    mma_f16(acc[mt][nt], af[mt], bf[nt]);
        }
    }

    // ---- epilogue: bias + activation, fp16 stores ----
    __half* __restrict__ outBuf = isZ ? g_C : g_G;
    const int row0 = m0 + wm * 64 + (lane >> 2);
    const int col0 = wn * 32 + 2 * (lane & 3);

    #pragma unroll
    for (int mt = 0; mt < 4; mt++) {
        #pragma unroll
        for (int nt = 0; nt < 4; nt++) {
            const int cl = col0 + nt * 8;
            const float b0v = sBias[cl];
            const float b1v = sBias[cl + 1];
            const int c = nbase + cl;
            #pragma unroll
            for (int half = 0; half < 2; half++) {
                const int rr = row0 + mt * 16 + half * 8;
                float v0 = acc[mt][nt][half * 2 + 0] + b0v;
                float v1 = acc[mt][nt][half * 2 + 1] + b1v;
                float o0, o1;
                if (isZ) {
                    o0 = sigmoidf_(-v0);
                    o1 = sigmoidf_(-v1);
                } else {
                    o0 = (v0 >= 0.f) ? (v0 + 0.5f) : sigmoidf_(v0);
                    o1 = (v1 >= 0.f) ? (v1 + 0.5f) : sigmoidf_(v1);
                }
                *reinterpret_cast<uint32_t*>(&outBuf[(size_t)rr * H_ + c]) = pack2h(o0, o1);
            }
        }
    }
}

// ----------------------------- scan phase A: per-chunk reduce -----------------------------
__global__ __launch_bounds__(256) void scan_phaseA()
{
    const int idx = blockIdx.x * 256 + threadIdx.x;     // 0 .. 65535
    const int h4 = idx & 127;
    const int ch = (idx >> 7) & (NC - 1);
    const int b  = idx >> 13;
    const uint2* C2 = reinterpret_cast<const uint2*>(g_C);
    const uint2* G2 = reinterpret_cast<const uint2*>(g_G);
    size_t p = ((size_t)(b * T_ + ch * LC) * H_) / 4 + h4;

    float4 A = make_float4(1.f,1.f,1.f,1.f);
    float4 s = make_float4(0.f,0.f,0.f,0.f);
    #pragma unroll 4
    for (int t = 0; t < LC; t++, p += H_/4) {
        const uint2 cu = C2[p];
        const uint2 gu = G2[p];
        const float2 c0 = __half22float2(*reinterpret_cast<const __half2*>(&cu.x));
        const float2 c1 = __half22float2(*reinterpret_cast<const __half2*>(&cu.y));
        const float2 g0 = __half22float2(*reinterpret_cast<const __half2*>(&gu.x));
        const float2 g1 = __half22float2(*reinterpret_cast<const __half2*>(&gu.y));
        s.x = c0.x*s.x + (1.f-c0.x)*g0.x;  A.x *= c0.x;
        s.y = c0.y*s.y + (1.f-c0.y)*g0.y;  A.y *= c0.y;
        s.z = c1.x*s.z + (1.f-c1.x)*g1.x;  A.z *= c1.x;
        s.w = c1.y*s.w + (1.f-c1.y)*g1.y;  A.w *= c1.y;
    }
    reinterpret_cast<float4*>(g_A)[idx] = A;
    reinterpret_cast<float4*>(g_S)[idx] = s;
}

// ----------------------------- scan phase B: warp-parallel chunk combine ----------------------
__global__ __launch_bounds__(256) void scan_phaseB(const float* __restrict__ h0)
{
    const int q    = blockIdx.x * 8 + (threadIdx.x >> 5);   // 0..1023
    const int lane = threadIdx.x & 31;
    const int b  = q >> 7;
    const int h4 = q & 127;

    const float4* A4 = reinterpret_cast<const float4*>(g_A);
    const float4* S4 = reinterpret_cast<const float4*>(g_S);
    float4* Hb4 = reinterpret_cast<float4*>(g_Hb);

    const int o0 = (b * NC + 2 * lane) * 128 + h4;
    const int o1 = o0 + 128;
    const float4 A0 = A4[o0], S0 = S4[o0];
    const float4 A1 = A4[o1], S1 = S4[o1];

    float4 Ap, Sp;
    Ap.x = A0.x*A1.x;  Sp.x = A1.x*S0.x + S1.x;
    Ap.y = A0.y*A1.y;  Sp.y = A1.y*S0.y + S1.y;
    Ap.z = A0.z*A1.z;  Sp.z = A1.z*S0.z + S1.z;
    Ap.w = A0.w*A1.w;  Sp.w = A1.w*S0.w + S1.w;

    #pragma unroll
    for (int d = 1; d < 32; d <<= 1) {
        float4 Au, Su;
        Au.x = __shfl_up_sync(0xFFFFFFFFu, Ap.x, d);
        Au.y = __shfl_up_sync(0xFFFFFFFFu, Ap.y, d);
        Au.z = __shfl_up_sync(0xFFFFFFFFu, Ap.z, d);
        Au.w = __shfl_up_sync(0xFFFFFFFFu, Ap.w, d);
        Su.x = __shfl_up_sync(0xFFFFFFFFu, Sp.x, d);
        Su.y = __shfl_up_sync(0xFFFFFFFFu, Sp.y, d);
        Su.z = __shfl_up_sync(0xFFFFFFFFu, Sp.z, d);
        Su.w = __shfl_up_sync(0xFFFFFFFFu, Sp.w, d);
        if (lane >= d) {
            Sp.x = Ap.x*Su.x + Sp.x;  Ap.x *= Au.x;
            Sp.y = Ap.y*Su.y + Sp.y;  Ap.y *= Au.y;
            Sp.z = Ap.z*Su.z + Sp.z;  Ap.z *= Au.z;
            Sp.w = Ap.w*Su.w + Sp.w;  Ap.w *= Au.w;
        }
    }

    float4 Ae, Se;
    Ae.x = __shfl_up_sync(0xFFFFFFFFu, Ap.x, 1);
    Ae.y = __shfl_up_sync(0xFFFFFFFFu, Ap.y, 1);
    Ae.z = __shfl_up_sync(0xFFFFFFFFu, Ap.z, 1);
    Ae.w = __shfl_up_sync(0xFFFFFFFFu, Ap.w, 1);
    Se.x = __shfl_up_sync(0xFFFFFFFFu, Sp.x, 1);
    Se.y = __shfl_up_sync(0xFFFFFFFFu, Sp.y, 1);
    Se.z = __shfl_up_sync(0xFFFFFFFFu, Sp.z, 1);
    Se.w = __shfl_up_sync(0xFFFFFFFFu, Sp.w, 1);
    if (lane == 0) {
        Ae = make_float4(1.f,1.f,1.f,1.f);
        Se = make_float4(0.f,0.f,0.f,0.f);
    }

    const float4 v = reinterpret_cast<const float4*>(h0)[b * 128 + h4];
    float4 s0;
    s0.x = (v.x >= 0.f) ? (v.x + 0.5f) : sigmoidf_(v.x);
    s0.y = (v.y >= 0.f) ? (v.y + 0.5f) : sigmoidf_(v.y);
    s0.z = (v.z >= 0.f) ? (v.z + 0.5f) : sigmoidf_(v.z);
    s0.w = (v.w >= 0.f) ? (v.w + 0.5f) : sigmoidf_(v.w);

    float4 st;
    st.x = Ae.x*s0.x + Se.x;
    st.y = Ae.y*s0.y + Se.y;
    st.z = Ae.z*s0.z + Se.z;
    st.w = Ae.w*s0.w + Se.w;
    Hb4[o0] = st;

    float4 st1;
    st1.x = A0.x*st.x + S0.x;
    st1.y = A0.y*st.y + S0.y;
    st1.z = A0.z*st.z + S0.z;
    st1.w = A0.w*st.w + S0.w;
    Hb4[o1] = st1;
}

// ----------------------------- scan phase C: rescan + output -----------------------------
__global__ __launch_bounds__(256) void scan_phaseC(float* __restrict__ out)
{
    const int idx = blockIdx.x * 256 + threadIdx.x;
    const int h4 = idx & 127;
    const int ch = (idx >> 7) & (NC - 1);
    const int b  = idx >> 13;
    const uint2* C2 = reinterpret_cast<const uint2*>(g_C);
    const uint2* G2 = reinterpret_cast<const uint2*>(g_G);
    float4* O4 = reinterpret_cast<float4*>(out);
    size_t p = ((size_t)(b * T_ + ch * LC) * H_) / 4 + h4;

    float4 st = reinterpret_cast<const float4*>(g_Hb)[(b * NC + ch) * 128 + h4];
    #pragma unroll 4
    for (int t = 0; t < LC; t++, p += H_/4) {
        const uint2 cu = C2[p];
        const uint2 gu = G2[p];
        const float2 c0 = __half22float2(*reinterpret_cast<const __half2*>(&cu.x));
        const float2 c1 = __half22float2(*reinterpret_cast<const __half2*>(&cu.y));
        const float2 g0 = __half22float2(*reinterpret_cast<const __half2*>(&gu.x));
        const float2 g1 = __half22float2(*reinterpret_cast<const __half2*>(&gu.y));
        st.x = c0.x*st.x + (1.f-c0.x)*g0.x;
        st.y = c0.y*st.y + (1.f-c0.y)*g0.y;
        st.z = c1.x*st.z + (1.f-c1.x)*g1.x;
        st.w = c1.y*st.w + (1.f-c1.y)*g1.y;
        O4[p] = st;
    }
}

extern "C" void kernel_launch(void* const* d_in, const int* in_sizes, int n_in,
                              void* d_out, int out_size)
{
    const float* x  = (const float*)d_in[0];
    const float* h0 = (const float*)d_in[1];
    const float* Wz = (const float*)d_in[2];
    const float* bz = (const float*)d_in[3];
    const float* Wh = (const float*)d_in[4];
    const float* bh = (const float*)d_in[5];
    float* out = (float*)d_out;

    cudaFuncSetAttribute(gemm_act_kernel, cudaFuncAttributeMaxDynamicSharedMemorySize, GEMM_SMEM);

    prep_kernel<<<(XBLOCKS + WBLOCKS) / 8, 256>>>(x, Wz, Wh);
    gemm_act_kernel<<<dim3(8, 256), 256, GEMM_SMEM>>>(bz, bh);
    scan_phaseA<<<256, 256>>>();
    scan_phaseB<<<128, 256>>>(h0);
    scan_phaseC<<<256, 256>>>(out);
}

// round 7
// speedup vs baseline: 2.1303x; 1.1033x over previous
#include <cuda_runtime.h>
#include <cuda_fp16.h>
#include <cstdint>

#define B_ 8
#define T_ 4096
#define D_ 512
#define H_ 512
#define M_ (B_*T_)      // 32768 rows
#define NC 64
#define LC (T_/NC)      // 64

// ----------------------------- scratch (device globals) -----------------------------
__device__ __half g_Xp[(size_t)M_*D_];  // [M/16][D/16][256]  (16m x 16k blocks, fragment order)
__device__ __half g_Wp[1024*512];       // [N/8][D/16][128]   (8n x 16k blocks, interleaved Wz/Wh)
__device__ __half2 g_CG[(size_t)M_*H_]; // (c,g) interleaved per (m,h)
__device__ float g_A[B_*NC*H_];
__device__ float g_S[B_*NC*H_];
__device__ float g_Hb[B_*NC*H_];

__device__ __forceinline__ float sigmoidf_(float x) { return 1.0f / (1.0f + __expf(-x)); }

__device__ __forceinline__ void mma_f16(float d[4], const uint32_t a[4], const uint32_t b[2]) {
    asm volatile(
        "mma.sync.aligned.m16n8k16.row.col.f32.f16.f16.f32 "
        "{%0,%1,%2,%3}, {%4,%5,%6,%7}, {%8,%9}, {%0,%1,%2,%3};\n"
        : "+f"(d[0]), "+f"(d[1]), "+f"(d[2]), "+f"(d[3])
        : "r"(a[0]), "r"(a[1]), "r"(a[2]), "r"(a[3]), "r"(b[0]), "r"(b[1]));
}

#define CP_ASYNC16(sa, gp) asm volatile("cp.async.cg.shared.global [%0], [%1], 16;" :: "r"(sa), "l"(__cvta_generic_to_global(gp)) : "memory")
#define CP_COMMIT()        asm volatile("cp.async.commit_group;" ::: "memory")
#define CP_WAIT2()         asm volatile("cp.async.wait_group 2;" ::: "memory")

__device__ __forceinline__ uint32_t smem_u32(const void* p) {
    uint32_t a;
    asm("{ .reg .u64 t; cvta.to.shared.u64 t, %1; cvt.u32.u64 %0, t; }" : "=r"(a) : "l"(p));
    return a;
}

__device__ __forceinline__ uint32_t pack2h(float a, float b) {
    __half2 h = __floats2half2_rn(a, b);
    return *reinterpret_cast<uint32_t*>(&h);
}

// ----------------------------- prep: f32 -> fp16 fragment pack -----------------------------
// W fused rows interleaved: fused row 2j = Wz[j], 2j+1 = Wh[j].
#define XBLOCKS ((M_/16)*(D_/16))    // 65536
#define WBLOCKS ((1024/8)*(D_/16))   // 4096

__global__ __launch_bounds__(256) void prep_kernel(
    const float* __restrict__ x, const float* __restrict__ Wz, const float* __restrict__ Wh)
{
    const int gw   = blockIdx.x * 8 + (threadIdx.x >> 5);
    const int lane = threadIdx.x & 31;
    const int r = lane >> 2, c = lane & 3;

    if (gw < XBLOCKS) {
        const int mb = gw >> 5;
        const int kb = gw & 31;
        const float* xp = x + (size_t)(mb * 16) * D_ + kb * 16;
        uint4 v;
        v.x = pack2h(xp[(size_t)r * D_ + 2*c],       xp[(size_t)r * D_ + 2*c + 1]);
        v.y = pack2h(xp[(size_t)(r+8) * D_ + 2*c],   xp[(size_t)(r+8) * D_ + 2*c + 1]);
        v.z = pack2h(xp[(size_t)r * D_ + 2*c + 8],   xp[(size_t)r * D_ + 2*c + 9]);
        v.w = pack2h(xp[(size_t)(r+8) * D_ + 2*c+8], xp[(size_t)(r+8) * D_ + 2*c + 9]);
        reinterpret_cast<uint4*>(g_Xp)[(size_t)gw * 32 + lane] = v;
    } else {
        const int wb = gw - XBLOCKS;
        const int nb = wb >> 5;
        const int kb = wb & 31;
        const int nf = nb * 8 + r;       // fused interleaved row in [0,1024)
        const int j  = nf >> 1;
        const float* Wrow = (nf & 1) ? (Wh + (size_t)j * D_) : (Wz + (size_t)j * D_);
        uint2 v;
        v.x = pack2h(Wrow[kb*16 + 2*c],     Wrow[kb*16 + 2*c + 1]);
        v.y = pack2h(Wrow[kb*16 + 2*c + 8], Wrow[kb*16 + 2*c + 9]);
        reinterpret_cast<uint2*>(g_Wp)[(size_t)wb * 32 + lane] = v;
    }
}

// ----------------------------- GEMM + activation + fused chunk-reduce -----------------------
#define KSTAGES 16
#define NBUF 4
#define A_STAGE_BYTES 8192
#define B_STAGE_BYTES 8192
#define STAGE_BYTES (A_STAGE_BYTES + B_STAGE_BYTES)
#define GEMM_SMEM (NBUF*STAGE_BYTES + 1024)   // 66560
// epilogue smem aliases (over dead stage buffers):
#define SCG_STRIDE 68                          // u32 per row (padded: conflict-free)
#define SCG_BYTES (128*SCG_STRIDE*4)           // 34816
#define PA_OFF 36864                           // partial A/S scratch (2KB)

__global__ __launch_bounds__(256, 2) void gemm_act_kernel(
    const float* __restrict__ bz, const float* __restrict__ bh)
{
    extern __shared__ char dyn[];
    float* sBias = reinterpret_cast<float*>(dyn + NBUF * STAGE_BYTES);
    const uint32_t sbase = smem_u32(dyn);

    const int tid  = threadIdx.x;
    const int wid  = tid >> 5;
    const int lane = tid & 31;
    const int wm = wid >> 2;
    const int wn = wid & 3;

    const int bn = blockIdx.x;   // 0..7 over fused-interleaved N=1024 (64 h each)
    const int bm = blockIdx.y;   // 0..255
    const int m0 = bm * 128;
    const int mb0 = bm * 8;
    const int nb0 = bn * 16;

    // interleaved bias: fused col cf -> (cf&1)? bh : bz at h = bn*64 + cf/2
    if (tid < 128) {
        const int h = bn * 64 + (tid >> 1);
        sBias[tid] = (tid & 1) ? bh[h] : bz[h];
    }

    float acc[4][4][4];
    #pragma unroll
    for (int i = 0; i < 4; i++)
        #pragma unroll
        for (int j = 0; j < 4; j++)
            #pragma unroll
            for (int q = 0; q < 4; q++) acc[i][j][q] = 0.f;

    auto load_stage = [&](int s, int buf) {
        const int kb0 = s * 2;
        const uint32_t stA = sbase + buf * STAGE_BYTES;
        const uint32_t stB = stA + A_STAGE_BYTES;
        #pragma unroll
        for (int i = 0; i < 2; i++) {
            const int seg = tid + i * 256;
            const int mbi = seg >> 6;
            const int w   = seg & 63;
            const __half* gp = g_Xp + ((size_t)(mb0 + mbi) * 32 + kb0) * 256 + w * 8;
            CP_ASYNC16(stA + seg * 16, gp);
        }
        #pragma unroll
        for (int i = 0; i < 2; i++) {
            const int seg = tid + i * 256;
            const int nbi = seg >> 5;
            const int w   = seg & 31;
            const __half* gp = g_Wp + ((size_t)(nb0 + nbi) * 32 + kb0) * 128 + w * 8;
            CP_ASYNC16(stB + seg * 16, gp);
        }
    };

    load_stage(0, 0); CP_COMMIT();
    load_stage(1, 1); CP_COMMIT();
    load_stage(2, 2); CP_COMMIT();

    for (int s = 0; s < KSTAGES; s++) {
        CP_WAIT2();
        __syncthreads();
        if (s + 3 < KSTAGES) load_stage(s + 3, (s + 3) & 3);
        CP_COMMIT();

        const char* stA = dyn + ((s & 3) * STAGE_BYTES);
        const char* stB = stA + A_STAGE_BYTES;

        #pragma unroll
        for (int ks = 0; ks < 2; ks++) {
            uint32_t af[4][4];
            uint32_t bf[4][2];
            #pragma unroll
            for (int mt = 0; mt < 4; mt++) {
                const int mb = wm * 4 + mt;
                const uint4 v = *reinterpret_cast<const uint4*>(stA + (mb * 2 + ks) * 512 + lane * 16);
                af[mt][0] = v.x; af[mt][1] = v.y; af[mt][2] = v.z; af[mt][3] = v.w;
            }
            #pragma unroll
            for (int nt = 0; nt < 4; nt++) {
                const int nb = wn * 4 + nt;
                const uint2 v = *reinterpret_cast<const uint2*>(stB + (nb * 2 + ks) * 256 + lane * 8);
                bf[nt][0] = v.x; bf[nt][1] = v.y;
            }
            #pragma unroll
            for (int mt = 0; mt < 4; mt++)
                #pragma unroll
                for (int nt = 0; nt < 4; nt++)
                    mma_f16(acc[mt][nt], af[mt], bf[nt]);
        }
    }

    // ---- epilogue: bias + activation; (c,g) -> global half2 + smem stage ----
    // pair (even,odd fused cols) = (z-input, h-input) for one h.
    uint32_t* sCG = reinterpret_cast<uint32_t*>(dyn);   // [128][SCG_STRIDE] u32 (half2)
    const int row0 = wm * 64 + (lane >> 2);             // local row 0..127
    const int col0 = wn * 32 + 2 * (lane & 3);          // even fused col

    #pragma unroll
    for (int mt = 0; mt < 4; mt++) {
        #pragma unroll
        for (int nt = 0; nt < 4; nt++) {
            const int cl = col0 + nt * 8;               // even fused col 0..126
            const int hl = cl >> 1;                     // h local 0..63
            const float b0v = sBias[cl];
            const float b1v = sBias[cl + 1];
            #pragma unroll
            for (int half = 0; half < 2; half++) {
                const int rl = row0 + mt * 16 + half * 8;     // local row
                const float v0 = acc[mt][nt][half * 2 + 0] + b0v;
                const float v1 = acc[mt][nt][half * 2 + 1] + b1v;
                const float c = sigmoidf_(-v0);
                const float g = (v1 >= 0.f) ? (v1 + 0.5f) : sigmoidf_(v1);
                const uint32_t cg = pack2h(c, g);
                reinterpret_cast<uint32_t*>(g_CG)[(size_t)(m0 + rl) * H_ + bn * 64 + hl] = cg;
                sCG[rl * SCG_STRIDE + hl] = cg;
            }
        }
    }
    __syncthreads();

    // ---- fused chunk reduce: 2 chunks x 64 h, 2 segments of 32 steps each ----
    {
        const int h   = tid & 63;
        const int seg = (tid >> 6) & 1;
        const int ch  = tid >> 7;
        float A = 1.f, S = 0.f;
        const int t0 = ch * 64 + seg * 32;
        #pragma unroll 8
        for (int t = 0; t < 32; t++) {
            const __half2 cgh = *reinterpret_cast<const __half2*>(&sCG[(t0 + t) * SCG_STRIDE + h]);
            const float2 f = __half22float2(cgh);
            S = f.x * S + (1.f - f.x) * f.y;
            A *= f.x;
        }
        float* pA = reinterpret_cast<float*>(dyn + PA_OFF);
        float* pS = pA + 256;
        pA[tid] = A; pS[tid] = S;
        __syncthreads();
        if (!seg) {
            const float A1 = pA[tid + 64], S1 = pS[tid + 64];
            const int b   = bm >> 5;
            const int chg = ((bm & 31) << 1) | ch;
            const int hg  = bn * 64 + h;
            g_A[(b * NC + chg) * H_ + hg] = A * A1;
            g_S[(b * NC + chg) * H_ + hg] = A1 * S + S1;
        }
    }
}

// ----------------------------- scan phase B: warp-parallel chunk combine ----------------------
__global__ __launch_bounds__(256) void scan_phaseB(const float* __restrict__ h0)
{
    const int q    = blockIdx.x * 8 + (threadIdx.x >> 5);   // 0..1023
    const int lane = threadIdx.x & 31;
    const int b  = q >> 7;
    const int h4 = q & 127;

    const float4* A4 = reinterpret_cast<const float4*>(g_A);
    const float4* S4 = reinterpret_cast<const float4*>(g_S);
    float4* Hb4 = reinterpret_cast<float4*>(g_Hb);

    const int o0 = (b * NC + 2 * lane) * 128 + h4;
    const int o1 = o0 + 128;
    const float4 A0 = A4[o0], S0 = S4[o0];
    const float4 A1 = A4[o1], S1 = S4[o1];

    float4 Ap, Sp;
    Ap.x = A0.x*A1.x;  Sp.x = A1.x*S0.x + S1.x;
    Ap.y = A0.y*A1.y;  Sp.y = A1.y*S0.y + S1.y;
    Ap.z = A0.z*A1.z;  Sp.z = A1.z*S0.z + S1.z;
    Ap.w = A0.w*A1.w;  Sp.w = A1.w*S0.w + S1.w;

    #pragma unroll
    for (int d = 1; d < 32; d <<= 1) {
        float4 Au, Su;
        Au.x = __shfl_up_sync(0xFFFFFFFFu, Ap.x, d);
        Au.y = __shfl_up_sync(0xFFFFFFFFu, Ap.y, d);
        Au.z = __shfl_up_sync(0xFFFFFFFFu, Ap.z, d);
        Au.w = __shfl_up_sync(0xFFFFFFFFu, Ap.w, d);
        Su.x = __shfl_up_sync(0xFFFFFFFFu, Sp.x, d);
        Su.y = __shfl_up_sync(0xFFFFFFFFu, Sp.y, d);
        Su.z = __shfl_up_sync(0xFFFFFFFFu, Sp.z, d);
        Su.w = __shfl_up_sync(0xFFFFFFFFu, Sp.w, d);
        if (lane >= d) {
            Sp.x = Ap.x*Su.x + Sp.x;  Ap.x *= Au.x;
            Sp.y = Ap.y*Su.y + Sp.y;  Ap.y *= Au.y;
            Sp.z = Ap.z*Su.z + Sp.z;  Ap.z *= Au.z;
            Sp.w = Ap.w*Su.w + Sp.w;  Ap.w *= Au.w;
        }
    }

    float4 Ae, Se;
    Ae.x = __shfl_up_sync(0xFFFFFFFFu, Ap.x, 1);
    Ae.y = __shfl_up_sync(0xFFFFFFFFu, Ap.y, 1);
    Ae.z = __shfl_up_sync(0xFFFFFFFFu, Ap.z, 1);
    Ae.w = __shfl_up_sync(0xFFFFFFFFu, Ap.w, 1);
    Se.x = __shfl_up_sync(0xFFFFFFFFu, Sp.x, 1);
    Se.y = __shfl_up_sync(0xFFFFFFFFu, Sp.y, 1);
    Se.z = __shfl_up_sync(0xFFFFFFFFu, Sp.z, 1);
    Se.w = __shfl_up_sync(0xFFFFFFFFu, Sp.w, 1);
    if (lane == 0) {
        Ae = make_float4(1.f,1.f,1.f,1.f);
        Se = make_float4(0.f,0.f,0.f,0.f);
    }

    const float4 v = reinterpret_cast<const float4*>(h0)[b * 128 + h4];
    float4 s0;
    s0.x = (v.x >= 0.f) ? (v.x + 0.5f) : sigmoidf_(v.x);
    s0.y = (v.y >= 0.f) ? (v.y + 0.5f) : sigmoidf_(v.y);
    s0.z = (v.z >= 0.f) ? (v.z + 0.5f) : sigmoidf_(v.z);
    s0.w = (v.w >= 0.f) ? (v.w + 0.5f) : sigmoidf_(v.w);

    float4 st;
    st.x = Ae.x*s0.x + Se.x;
    st.y = Ae.y*s0.y + Se.y;
    st.z = Ae.z*s0.z + Se.z;
    st.w = Ae.w*s0.w + Se.w;
    Hb4[o0] = st;

    float4 st1;
    st1.x = A0.x*st.x + S0.x;
    st1.y = A0.y*st.y + S0.y;
    st1.z = A0.z*st.z + S0.z;
    st1.w = A0.w*st.w + S0.w;
    Hb4[o1] = st1;
}

// ----------------------------- scan phase C: rescan + output -----------------------------
__global__ __launch_bounds__(256) void scan_phaseC(float* __restrict__ out)
{
    const int idx = blockIdx.x * 256 + threadIdx.x;
    const int h4 = idx & 127;
    const int ch = (idx >> 7) & (NC - 1);
    const int b  = idx >> 13;
    const uint4* CG4 = reinterpret_cast<const uint4*>(g_CG);
    float4* O4 = reinterpret_cast<float4*>(out);
    size_t p = ((size_t)(b * T_ + ch * LC) * H_) / 4 + h4;

    float4 st = reinterpret_cast<const float4*>(g_Hb)[(b * NC + ch) * 128 + h4];
    #pragma unroll 4
    for (int t = 0; t < LC; t++, p += H_/4) {
        const uint4 u = CG4[p];
        const float2 a0 = __half22float2(*reinterpret_cast<const __half2*>(&u.x));
        const float2 a1 = __half22float2(*reinterpret_cast<const __half2*>(&u.y));
        const float2 a2 = __half22float2(*reinterpret_cast<const __half2*>(&u.z));
        const float2 a3 = __half22float2(*reinterpret_cast<const __half2*>(&u.w));
        st.x = a0.x*st.x + (1.f-a0.x)*a0.y;
        st.y = a1.x*st.y + (1.f-a1.x)*a1.y;
        st.z = a2.x*st.z + (1.f-a2.x)*a2.y;
        st.w = a3.x*st.w + (1.f-a3.x)*a3.y;
        O4[p] = st;
    }
}

extern "C" void kernel_launch(void* const* d_in, const int* in_sizes, int n_in,
                              void* d_out, int out_size)
{
    const float* x  = (const float*)d_in[0];
    const float* h0 = (const float*)d_in[1];
    const float* Wz = (const float*)d_in[2];
    const float* bz = (const float*)d_in[3];
    const float* Wh = (const float*)d_in[4];
    const float* bh = (const float*)d_in[5];
    float* out = (float*)d_out;

    cudaFuncSetAttribute(gemm_act_kernel, cudaFuncAttributeMaxDynamicSharedMemorySize, GEMM_SMEM);

    prep_kernel<<<(XBLOCKS + WBLOCKS) / 8, 256>>>(x, Wz, Wh);
    gemm_act_kernel<<<dim3(8, 256), 256, GEMM_SMEM>>>(bz, bh);
    scan_phaseB<<<128, 256>>>(h0);
    scan_phaseC<<<256, 256>>>(out);
}

// round 8
// speedup vs baseline: 2.1621x; 1.0149x over previous
#include <cuda_runtime.h>
#include <cuda_fp16.h>
#include <cstdint>

#define B_ 8
#define T_ 4096
#define D_ 512
#define H_ 512
#define M_ (B_*T_)      // 32768 rows
#define NC 128          // chunks per sequence
#define LC (T_/NC)      // 32 steps per chunk

// ----------------------------- scratch (device globals) -----------------------------
__device__ __half g_Xp[(size_t)M_*D_];  // [M/16][D/16][256]  (16m x 16k blocks, fragment order)
__device__ __half g_Wp[1024*512];       // [N/8][D/16][128]   (8n x 16k blocks, interleaved Wz/Wh)
__device__ __half2 g_CG[(size_t)M_*H_]; // (c,g) interleaved per (m,h)
__device__ float g_A[B_*NC*H_];
__device__ float g_S[B_*NC*H_];
__device__ float g_Hb[B_*NC*H_];

__device__ __forceinline__ float sigmoidf_(float x) { return 1.0f / (1.0f + __expf(-x)); }

__device__ __forceinline__ void mma_f16(float d[4], const uint32_t a[4], const uint32_t b[2]) {
    asm volatile(
        "mma.sync.aligned.m16n8k16.row.col.f32.f16.f16.f32 "
        "{%0,%1,%2,%3}, {%4,%5,%6,%7}, {%8,%9}, {%0,%1,%2,%3};\n"
        : "+f"(d[0]), "+f"(d[1]), "+f"(d[2]), "+f"(d[3])
        : "r"(a[0]), "r"(a[1]), "r"(a[2]), "r"(a[3]), "r"(b[0]), "r"(b[1]));
}

#define CP_ASYNC16(sa, gp) asm volatile("cp.async.cg.shared.global [%0], [%1], 16;" :: "r"(sa), "l"(__cvta_generic_to_global(gp)) : "memory")
#define CP_COMMIT()        asm volatile("cp.async.commit_group;" ::: "memory")
#define CP_WAIT2()         asm volatile("cp.async.wait_group 2;" ::: "memory")

__device__ __forceinline__ uint32_t smem_u32(const void* p) {
    uint32_t a;
    asm("{ .reg .u64 t; cvta.to.shared.u64 t, %1; cvt.u32.u64 %0, t; }" : "=r"(a) : "l"(p));
    return a;
}

__device__ __forceinline__ uint32_t pack2h(float a, float b) {
    __half2 h = __floats2half2_rn(a, b);
    return *reinterpret_cast<uint32_t*>(&h);
}

// ----------------------------- prep: f32 -> fp16 fragment pack -----------------------------
// W fused rows interleaved: fused row 2j = Wz[j], 2j+1 = Wh[j].
#define XBLOCKS ((M_/16)*(D_/16))    // 65536
#define WBLOCKS ((1024/8)*(D_/16))   // 4096

__global__ __launch_bounds__(256) void prep_kernel(
    const float* __restrict__ x, const float* __restrict__ Wz, const float* __restrict__ Wh)
{
    const int gw   = blockIdx.x * 8 + (threadIdx.x >> 5);
    const int lane = threadIdx.x & 31;
    const int r = lane >> 2, c = lane & 3;

    if (gw < XBLOCKS) {
        const int mb = gw >> 5;
        const int kb = gw & 31;
        const float* xp = x + (size_t)(mb * 16) * D_ + kb * 16;
        uint4 v;
        v.x = pack2h(xp[(size_t)r * D_ + 2*c],       xp[(size_t)r * D_ + 2*c + 1]);
        v.y = pack2h(xp[(size_t)(r+8) * D_ + 2*c],   xp[(size_t)(r+8) * D_ + 2*c + 1]);
        v.z = pack2h(xp[(size_t)r * D_ + 2*c + 8],   xp[(size_t)r * D_ + 2*c + 9]);
        v.w = pack2h(xp[(size_t)(r+8) * D_ + 2*c+8], xp[(size_t)(r+8) * D_ + 2*c + 9]);
        reinterpret_cast<uint4*>(g_Xp)[(size_t)gw * 32 + lane] = v;
    } else {
        const int wb = gw - XBLOCKS;
        const int nb = wb >> 5;
        const int kb = wb & 31;
        const int nf = nb * 8 + r;       // fused interleaved row in [0,1024)
        const int j  = nf >> 1;
        const float* Wrow = (nf & 1) ? (Wh + (size_t)j * D_) : (Wz + (size_t)j * D_);
        uint2 v;
        v.x = pack2h(Wrow[kb*16 + 2*c],     Wrow[kb*16 + 2*c + 1]);
        v.y = pack2h(Wrow[kb*16 + 2*c + 8], Wrow[kb*16 + 2*c + 9]);
        reinterpret_cast<uint2*>(g_Wp)[(size_t)wb * 32 + lane] = v;
    }
}

// ----------------------------- GEMM + activation + fused chunk-reduce -----------------------
#define KSTAGES 16
#define NBUF 4
#define A_STAGE_BYTES 8192
#define B_STAGE_BYTES 8192
#define STAGE_BYTES (A_STAGE_BYTES + B_STAGE_BYTES)
#define GEMM_SMEM (NBUF*STAGE_BYTES + 1024)   // 66560
// epilogue smem alias (over dead stage buffers):
#define SCG_STRIDE 68                          // u32 per row (padded: conflict-free)

__global__ __launch_bounds__(256, 2) void gemm_act_kernel(
    const float* __restrict__ bz, const float* __restrict__ bh)
{
    extern __shared__ char dyn[];
    float* sBias = reinterpret_cast<float*>(dyn + NBUF * STAGE_BYTES);
    const uint32_t sbase = smem_u32(dyn);

    const int tid  = threadIdx.x;
    const int wid  = tid >> 5;
    const int lane = tid & 31;
    const int wm = wid >> 2;
    const int wn = wid & 3;

    const int bn = blockIdx.x;   // 0..7 over fused-interleaved N=1024 (64 h each)
    const int bm = blockIdx.y;   // 0..255
    const int m0 = bm * 128;
    const int mb0 = bm * 8;
    const int nb0 = bn * 16;

    // interleaved bias: fused col cf -> (cf&1)? bh : bz at h = bn*64 + cf/2
    if (tid < 128) {
        const int h = bn * 64 + (tid >> 1);
        sBias[tid] = (tid & 1) ? bh[h] : bz[h];
    }

    float acc[4][4][4];
    #pragma unroll
    for (int i = 0; i < 4; i++)
        #pragma unroll
        for (int j = 0; j < 4; j++)
            #pragma unroll
            for (int q = 0; q < 4; q++) acc[i][j][q] = 0.f;

    auto load_stage = [&](int s, int buf) {
        const int kb0 = s * 2;
        const uint32_t stA = sbase + buf * STAGE_BYTES;
        const uint32_t stB = stA + A_STAGE_BYTES;
        #pragma unroll
        for (int i = 0; i < 2; i++) {
            const int seg = tid + i * 256;
            const int mbi = seg >> 6;
            const int w   = seg & 63;
            const __half* gp = g_Xp + ((size_t)(mb0 + mbi) * 32 + kb0) * 256 + w * 8;
            CP_ASYNC16(stA + seg * 16, gp);
        }
        #pragma unroll
        for (int i = 0; i < 2; i++) {
            const int seg = tid + i * 256;
            const int nbi = seg >> 5;
            const int w   = seg & 31;
            const __half* gp = g_Wp + ((size_t)(nb0 + nbi) * 32 + kb0) * 128 + w * 8;
            CP_ASYNC16(stB + seg * 16, gp);
        }
    };

    load_stage(0, 0); CP_COMMIT();
    load_stage(1, 1); CP_COMMIT();
    load_stage(2, 2); CP_COMMIT();

    for (int s = 0; s < KSTAGES; s++) {
        CP_WAIT2();
        __syncthreads();
        if (s + 3 < KSTAGES) load_stage(s + 3, (s + 3) & 3);
        CP_COMMIT();

        const char* stA = dyn + ((s & 3) * STAGE_BYTES);
        const char* stB = stA + A_STAGE_BYTES;

        #pragma unroll
        for (int ks = 0; ks < 2; ks++) {
            uint32_t af[4][4];
            uint32_t bf[4][2];
            #pragma unroll
            for (int mt = 0; mt < 4; mt++) {
                const int mb = wm * 4 + mt;
                const uint4 v = *reinterpret_cast<const uint4*>(stA + (mb * 2 + ks) * 512 + lane * 16);
                af[mt][0] = v.x; af[mt][1] = v.y; af[mt][2] = v.z; af[mt][3] = v.w;
            }
            #pragma unroll
            for (int nt = 0; nt < 4; nt++) {
                const int nb = wn * 4 + nt;
                const uint2 v = *reinterpret_cast<const uint2*>(stB + (nb * 2 + ks) * 256 + lane * 8);
                bf[nt][0] = v.x; bf[nt][1] = v.y;
            }
            #pragma unroll
            for (int mt = 0; mt < 4; mt++)
                #pragma unroll
                for (int nt = 0; nt < 4; nt++)
                    mma_f16(acc[mt][nt], af[mt], bf[nt]);
        }
    }

    // ---- epilogue: bias + activation; (c,g) -> global half2 + smem stage ----
    uint32_t* sCG = reinterpret_cast<uint32_t*>(dyn);   // [128][SCG_STRIDE] u32 (half2)
    const int row0 = wm * 64 + (lane >> 2);             // local row 0..127
    const int col0 = wn * 32 + 2 * (lane & 3);          // even fused col

    #pragma unroll
    for (int mt = 0; mt < 4; mt++) {
        #pragma unroll
        for (int nt = 0; nt < 4; nt++) {
            const int cl = col0 + nt * 8;               // even fused col 0..126
            const int hl = cl >> 1;                     // h local 0..63
            const float b0v = sBias[cl];
            const float b1v = sBias[cl + 1];
            #pragma unroll
            for (int half = 0; half < 2; half++) {
                const int rl = row0 + mt * 16 + half * 8;     // local row
                const float v0 = acc[mt][nt][half * 2 + 0] + b0v;
                const float v1 = acc[mt][nt][half * 2 + 1] + b1v;
                const float c = sigmoidf_(-v0);
                const float g = (v1 >= 0.f) ? (v1 + 0.5f) : sigmoidf_(v1);
                const uint32_t cg = pack2h(c, g);
                reinterpret_cast<uint32_t*>(g_CG)[(size_t)(m0 + rl) * H_ + bn * 64 + hl] = cg;
                sCG[rl * SCG_STRIDE + hl] = cg;
            }
        }
    }
    __syncthreads();

    // ---- fused chunk reduce: tile = 4 chunks of 32 rows; one (chunk,h) per thread ----
    {
        const int h   = tid & 63;
        const int seg = tid >> 6;          // 0..3 chunk within tile
        float A = 1.f, S = 0.f;
        const int t0 = seg * 32;
        #pragma unroll 8
        for (int t = 0; t < 32; t++) {
            const __half2 cgh = *reinterpret_cast<const __half2*>(&sCG[(t0 + t) * SCG_STRIDE + h]);
            const float2 f = __half22float2(cgh);
            S = f.x * S + (1.f - f.x) * f.y;
            A *= f.x;
        }
        const int b   = bm >> 5;                 // 32 bm tiles per batch
        const int chg = ((bm & 31) << 2) | seg;  // global chunk 0..127
        const int hg  = bn * 64 + h;
        g_A[(b * NC + chg) * H_ + hg] = A;
        g_S[(b * NC + chg) * H_ + hg] = S;
    }
}

// ----------------------------- scan phase B: warp-parallel chunk combine ----------------------
// One warp per (b, h-quad). Lane l covers chunks 4l..4l+3.
__global__ __launch_bounds__(256) void scan_phaseB(const float* __restrict__ h0)
{
    const int q    = blockIdx.x * 8 + (threadIdx.x >> 5);   // 0..1023
    const int lane = threadIdx.x & 31;
    const int b  = q >> 7;
    const int h4 = q & 127;

    const float4* A4 = reinterpret_cast<const float4*>(g_A);
    const float4* S4 = reinterpret_cast<const float4*>(g_S);
    float4* Hb4 = reinterpret_cast<float4*>(g_Hb);

    const int ob = (b * NC + 4 * lane) * 128 + h4;
    float4 Ai[4], Si[4];
    #pragma unroll
    for (int i = 0; i < 4; i++) {
        Ai[i] = A4[ob + i * 128];
        Si[i] = S4[ob + i * 128];
    }

    // compose the lane's 4 chunks in order
    float4 Ap = Ai[0], Sp = Si[0];
    #pragma unroll
    for (int i = 1; i < 4; i++) {
        Sp.x = Ai[i].x*Sp.x + Si[i].x;  Ap.x *= Ai[i].x;
        Sp.y = Ai[i].y*Sp.y + Si[i].y;  Ap.y *= Ai[i].y;
        Sp.z = Ai[i].z*Sp.z + Si[i].z;  Ap.z *= Ai[i].z;
        Sp.w = Ai[i].w*Sp.w + Si[i].w;  Ap.w *= Ai[i].w;
    }

    // inclusive warp scan
    #pragma unroll
    for (int d = 1; d < 32; d <<= 1) {
        float4 Au, Su;
        Au.x = __shfl_up_sync(0xFFFFFFFFu, Ap.x, d);
        Au.y = __shfl_up_sync(0xFFFFFFFFu, Ap.y, d);
        Au.z = __shfl_up_sync(0xFFFFFFFFu, Ap.z, d);
        Au.w = __shfl_up_sync(0xFFFFFFFFu, Ap.w, d);
        Su.x = __shfl_up_sync(0xFFFFFFFFu, Sp.x, d);
        Su.y = __shfl_up_sync(0xFFFFFFFFu, Sp.y, d);
        Su.z = __shfl_up_sync(0xFFFFFFFFu, Sp.z, d);
        Su.w = __shfl_up_sync(0xFFFFFFFFu, Sp.w, d);
        if (lane >= d) {
            Sp.x = Ap.x*Su.x + Sp.x;  Ap.x *= Au.x;
            Sp.y = Ap.y*Su.y + Sp.y;  Ap.y *= Au.y;
            Sp.z = Ap.z*Su.z + Sp.z;  Ap.z *= Au.z;
            Sp.w = Ap.w*Su.w + Sp.w;  Ap.w *= Au.w;
        }
    }

    // exclusive prefix
    float4 Ae, Se;
    Ae.x = __shfl_up_sync(0xFFFFFFFFu, Ap.x, 1);
    Ae.y = __shfl_up_sync(0xFFFFFFFFu, Ap.y, 1);
    Ae.z = __shfl_up_sync(0xFFFFFFFFu, Ap.z, 1);
    Ae.w = __shfl_up_sync(0xFFFFFFFFu, Ap.w, 1);
    Se.x = __shfl_up_sync(0xFFFFFFFFu, Sp.x, 1);
    Se.y = __shfl_up_sync(0xFFFFFFFFu, Sp.y, 1);
    Se.z = __shfl_up_sync(0xFFFFFFFFu, Sp.z, 1);
    Se.w = __shfl_up_sync(0xFFFFFFFFu, Sp.w, 1);
    if (lane == 0) {
        Ae = make_float4(1.f,1.f,1.f,1.f);
        Se = make_float4(0.f,0.f,0.f,0.f);
    }

    // initial state g(h0)
    const float4 v = reinterpret_cast<const float4*>(h0)[b * 128 + h4];
    float4 st;
    st.x = (v.x >= 0.f) ? (v.x + 0.5f) : sigmoidf_(v.x);
    st.y = (v.y >= 0.f) ? (v.y + 0.5f) : sigmoidf_(v.y);
    st.z = (v.z >= 0.f) ? (v.z + 0.5f) : sigmoidf_(v.z);
    st.w = (v.w >= 0.f) ? (v.w + 0.5f) : sigmoidf_(v.w);

    st.x = Ae.x*st.x + Se.x;
    st.y = Ae.y*st.y + Se.y;
    st.z = Ae.z*st.z + Se.z;
    st.w = Ae.w*st.w + Se.w;

    #pragma unroll
    for (int i = 0; i < 4; i++) {
        Hb4[ob + i * 128] = st;
        st.x = Ai[i].x*st.x + Si[i].x;
        st.y = Ai[i].y*st.y + Si[i].y;
        st.z = Ai[i].z*st.z + Si[i].z;
        st.w = Ai[i].w*st.w + Si[i].w;
    }
}

// ----------------------------- scan phase C: rescan + output -----------------------------
__global__ __launch_bounds__(256) void scan_phaseC(float* __restrict__ out)
{
    const int idx = blockIdx.x * 256 + threadIdx.x;     // 0 .. 131071
    const int h4 = idx & 127;
    const int ch = (idx >> 7) & (NC - 1);
    const int b  = idx >> 14;
    const uint4* CG4 = reinterpret_cast<const uint4*>(g_CG);
    float4* O4 = reinterpret_cast<float4*>(out);
    size_t p = ((size_t)(b * T_ + ch * LC) * H_) / 4 + h4;

    float4 st = reinterpret_cast<const float4*>(g_Hb)[(b * NC + ch) * 128 + h4];
    #pragma unroll 4
    for (int t = 0; t < LC; t++, p += H_/4) {
        const uint4 u = CG4[p];
        const float2 a0 = __half22float2(*reinterpret_cast<const __half2*>(&u.x));
        const float2 a1 = __half22float2(*reinterpret_cast<const __half2*>(&u.y));
        const float2 a2 = __half22float2(*reinterpret_cast<const __half2*>(&u.z));
        const float2 a3 = __half22float2(*reinterpret_cast<const __half2*>(&u.w));
        st.x = a0.x*st.x + (1.f-a0.x)*a0.y;
        st.y = a1.x*st.y + (1.f-a1.x)*a1.y;
        st.z = a2.x*st.z + (1.f-a2.x)*a2.y;
        st.w = a3.x*st.w + (1.f-a3.x)*a3.y;
        O4[p] = st;
    }
}

extern "C" void kernel_launch(void* const* d_in, const int* in_sizes, int n_in,
                              void* d_out, int out_size)
{
    const float* x  = (const float*)d_in[0];
    const float* h0 = (const float*)d_in[1];
    const float* Wz = (const float*)d_in[2];
    const float* bz = (const float*)d_in[3];
    const float* Wh = (const float*)d_in[4];
    const float* bh = (const float*)d_in[5];
    float* out = (float*)d_out;

    cudaFuncSetAttribute(gemm_act_kernel, cudaFuncAttributeMaxDynamicSharedMemorySize, GEMM_SMEM);

    prep_kernel<<<(XBLOCKS + WBLOCKS) / 8, 256>>>(x, Wz, Wh);
    gemm_act_kernel<<<dim3(8, 256), 256, GEMM_SMEM>>>(bz, bh);
    scan_phaseB<<<128, 256>>>(h0);
    scan_phaseC<<<512, 256>>>(out);
}

// round 9
// speedup vs baseline: 2.3464x; 1.0853x over previous
#include <cuda_runtime.h>
#include <cuda_fp16.h>
#include <cstdint>

#define B_ 8
#define T_ 4096
#define D_ 512
#define H_ 512
#define M_ (B_*T_)      // 32768 rows
#define NC 128          // chunks per sequence
#define LC (T_/NC)      // 32 steps per chunk

// ----------------------------- scratch (device globals) -----------------------------
__device__ __half g_Xp[(size_t)M_*D_];  // [M/16][D/16][256] (16m x 16k blocks, fragment order)
__device__ __half g_Wp[1024*512];       // [N/16 pairs][D/16][256] (paired 8n blocks, interleaved Wz/Wh)
__device__ __half2 g_CG[(size_t)M_*H_]; // (c,g) interleaved per (m,h)
__device__ float g_A[B_*NC*H_];
__device__ float g_S[B_*NC*H_];
__device__ float g_Hb[B_*NC*H_];

__device__ __forceinline__ float sigmoidf_(float x) { return 1.0f / (1.0f + __expf(-x)); }

__device__ __forceinline__ void mma_f16(float d[4], const uint32_t a[4], const uint32_t b[2]) {
    asm volatile(
        "mma.sync.aligned.m16n8k16.row.col.f32.f16.f16.f32 "
        "{%0,%1,%2,%3}, {%4,%5,%6,%7}, {%8,%9}, {%0,%1,%2,%3};\n"
        : "+f"(d[0]), "+f"(d[1]), "+f"(d[2]), "+f"(d[3])
        : "r"(a[0]), "r"(a[1]), "r"(a[2]), "r"(a[3]), "r"(b[0]), "r"(b[1]));
}

#define CP_ASYNC16(sa, gp) asm volatile("cp.async.cg.shared.global [%0], [%1], 16;" :: "r"(sa), "l"(__cvta_generic_to_global(gp)) : "memory")
#define CP_COMMIT()        asm volatile("cp.async.commit_group;" ::: "memory")
#define CP_WAIT1()         asm volatile("cp.async.wait_group 1;" ::: "memory")

__device__ __forceinline__ uint32_t smem_u32(const void* p) {
    uint32_t a;
    asm("{ .reg .u64 t; cvta.to.shared.u64 t, %1; cvt.u32.u64 %0, t; }" : "=r"(a) : "l"(p));
    return a;
}

__device__ __forceinline__ uint32_t pack2h(float a, float b) {
    __half2 h = __floats2half2_rn(a, b);
    return *reinterpret_cast<uint32_t*>(&h);
}

// ----------------------------- prep: f32 -> fp16 fragment pack -----------------------------
// X: warp per (mb,kb) 16x16 block (as before).
// W: warp per (pair pb, kb): pair of 8-n fused blocks; lane writes uint4
//    {even-block frag (8B), odd-block frag (8B)}. Fused row 2j = Wz[j], 2j+1 = Wh[j].
#define XBLOCKS ((M_/16)*(D_/16))    // 65536
#define WPAIRS ((1024/16)*(D_/16))   // 2048

__global__ __launch_bounds__(256) void prep_kernel(
    const float* __restrict__ x, const float* __restrict__ Wz, const float* __restrict__ Wh)
{
    const int gw   = blockIdx.x * 8 + (threadIdx.x >> 5);
    const int lane = threadIdx.x & 31;
    const int r = lane >> 2, c = lane & 3;

    if (gw < XBLOCKS) {
        const int mb = gw >> 5;
        const int kb = gw & 31;
        const float* xp = x + (size_t)(mb * 16) * D_ + kb * 16;
        uint4 v;
        v.x = pack2h(xp[(size_t)r * D_ + 2*c],       xp[(size_t)r * D_ + 2*c + 1]);
        v.y = pack2h(xp[(size_t)(r+8) * D_ + 2*c],   xp[(size_t)(r+8) * D_ + 2*c + 1]);
        v.z = pack2h(xp[(size_t)r * D_ + 2*c + 8],   xp[(size_t)r * D_ + 2*c + 9]);
        v.w = pack2h(xp[(size_t)(r+8) * D_ + 2*c+8], xp[(size_t)(r+8) * D_ + 2*c + 9]);
        reinterpret_cast<uint4*>(g_Xp)[(size_t)gw * 32 + lane] = v;
    } else {
        const int wp = gw - XBLOCKS;     // 0..2047
        const int pb = wp >> 5;          // pair index 0..63
        const int kb = wp & 31;
        // even block fused row, odd block fused row (same lane role r in both)
        const int nfe = pb * 16 + r;         // even 8-block
        const int nfo = pb * 16 + 8 + r;     // odd 8-block
        const float* We = (nfe & 1) ? (Wh + (size_t)(nfe >> 1) * D_) : (Wz + (size_t)(nfe >> 1) * D_);
        const float* Wo = (nfo & 1) ? (Wh + (size_t)(nfo >> 1) * D_) : (Wz + (size_t)(nfo >> 1) * D_);
        uint4 v;
        v.x = pack2h(We[kb*16 + 2*c],     We[kb*16 + 2*c + 1]);
        v.y = pack2h(We[kb*16 + 2*c + 8], We[kb*16 + 2*c + 9]);
        v.z = pack2h(Wo[kb*16 + 2*c],     Wo[kb*16 + 2*c + 1]);
        v.w = pack2h(Wo[kb*16 + 2*c + 8], Wo[kb*16 + 2*c + 9]);
        reinterpret_cast<uint4*>(g_Wp)[(size_t)wp * 32 + lane] = v;
    }
}

// ----------------------------- GEMM + activation + fused chunk-reduce -----------------------
// CTA tile 128m x 128n; stage K=64 (4 k-blocks); 8 stages; NBUF=3 (96KB smem, 2 CTAs/SM).
#define KSTAGES 8
#define NBUF 3
#define A_STAGE_BYTES 16384     // 8 mblocks x 4 kblocks x 512B
#define B_STAGE_BYTES 16384     // 8 pairs   x 4 kblocks x 512B
#define STAGE_BYTES (A_STAGE_BYTES + B_STAGE_BYTES)
#define GEMM_SMEM (NBUF*STAGE_BYTES + 1024)   // 99328
#define SCG_STRIDE 68                          // u32 per row (padded)

__global__ __launch_bounds__(256, 2) void gemm_act_kernel(
    const float* __restrict__ bz, const float* __restrict__ bh)
{
    extern __shared__ char dyn[];
    float* sBias = reinterpret_cast<float*>(dyn + NBUF * STAGE_BYTES);
    const uint32_t sbase = smem_u32(dyn);

    const int tid  = threadIdx.x;
    const int wid  = tid >> 5;
    const int lane = tid & 31;
    const int wm = wid >> 2;
    const int wn = wid & 3;

    const int bn = blockIdx.x;   // 0..7 over fused-interleaved N=1024 (64 h each)
    const int bm = blockIdx.y;   // 0..255
    const int m0 = bm * 128;
    const int mb0 = bm * 8;
    const int pb0 = bn * 8;      // first n-pair (16 fused n per pair)

    if (tid < 128) {
        const int h = bn * 64 + (tid >> 1);
        sBias[tid] = (tid & 1) ? bh[h] : bz[h];
    }

    float acc[4][4][4];
    #pragma unroll
    for (int i = 0; i < 4; i++)
        #pragma unroll
        for (int j = 0; j < 4; j++)
            #pragma unroll
            for (int q = 0; q < 4; q++) acc[i][j][q] = 0.f;

    // stage loader: 32KB per stage (A 16KB + B 16KB), 2048 segs / 256 threads = 8 iters
    auto load_stage = [&](int s, int buf) {
        const int kb0 = s * 4;
        const uint32_t stA = sbase + buf * STAGE_BYTES;
        const uint32_t stB = stA + A_STAGE_BYTES;
        #pragma unroll
        for (int i = 0; i < 4; i++) {            // A: 1024 segs of 16B
            const int seg = tid + i * 256;
            const int mbi = seg >> 7;            // 128 segs per m-block (2KB)
            const int w   = seg & 127;
            const __half* gp = g_Xp + ((size_t)(mb0 + mbi) * 32 + kb0) * 256 + w * 8;
            CP_ASYNC16(stA + seg * 16, gp);
        }
        #pragma unroll
        for (int i = 0; i < 4; i++) {            // B: 1024 segs of 16B
            const int seg = tid + i * 256;
            const int pbi = seg >> 7;            // 128 segs per pair (2KB)
            const int w   = seg & 127;
            const __half* gp = g_Wp + ((size_t)(pb0 + pbi) * 32 + kb0) * 256 + w * 8;
            CP_ASYNC16(stB + seg * 16, gp);
        }
    };

    load_stage(0, 0); CP_COMMIT();
    load_stage(1, 1); CP_COMMIT();

    int bufC = 0;           // buffer of stage s
    int bufL = 2;           // buffer for stage s+2
    for (int s = 0; s < KSTAGES; s++) {
        CP_WAIT1();
        __syncthreads();
        if (s + 2 < KSTAGES) load_stage(s + 2, bufL);
        CP_COMMIT();

        const char* stA = dyn + bufC * STAGE_BYTES;
        const char* stB = stA + A_STAGE_BYTES;
        bufL = bufC;
        bufC = (bufC == 2) ? 0 : bufC + 1;

        #pragma unroll
        for (int ks = 0; ks < 4; ks++) {
            uint32_t af[4][4];
            uint32_t bf[4][2];
            #pragma unroll
            for (int mt = 0; mt < 4; mt++) {
                const int mb = wm * 4 + mt;
                const uint4 v = *reinterpret_cast<const uint4*>(stA + (mb * 4 + ks) * 512 + lane * 16);
                af[mt][0] = v.x; af[mt][1] = v.y; af[mt][2] = v.z; af[mt][3] = v.w;
            }
            #pragma unroll
            for (int i = 0; i < 2; i++) {
                const int pbl = wn * 2 + i;
                const uint4 v = *reinterpret_cast<const uint4*>(stB + (pbl * 4 + ks) * 512 + lane * 16);
                bf[2*i][0]   = v.x; bf[2*i][1]   = v.y;
                bf[2*i+1][0] = v.z; bf[2*i+1][1] = v.w;
            }
            #pragma unroll
            for (int mt = 0; mt < 4; mt++)
                #pragma unroll
                for (int nt = 0; nt < 4; nt++)
                    mma_f16(acc[mt][nt], af[mt], bf[nt]);
        }
    }

    __syncthreads();   // all warps done reading stage smem before sCG overwrite

    // ---- epilogue: bias + activation; (c,g) -> global half2 + smem stage ----
    uint32_t* sCG = reinterpret_cast<uint32_t*>(dyn);   // [128][SCG_STRIDE] u32 (half2)
    const int row0 = wm * 64 + (lane >> 2);
    const int col0 = wn * 32 + 2 * (lane & 3);

    #pragma unroll
    for (int mt = 0; mt < 4; mt++) {
        #pragma unroll
        for (int nt = 0; nt < 4; nt++) {
            const int cl = col0 + nt * 8;               // even fused col 0..126
            const int hl = cl >> 1;                     // h local 0..63
            const float b0v = sBias[cl];
            const float b1v = sBias[cl + 1];
            #pragma unroll
            for (int half = 0; half < 2; half++) {
                const int rl = row0 + mt * 16 + half * 8;
                const float v0 = acc[mt][nt][half * 2 + 0] + b0v;
                const float v1 = acc[mt][nt][half * 2 + 1] + b1v;
                const float c = sigmoidf_(-v0);
                const float g = (v1 >= 0.f) ? (v1 + 0.5f) : sigmoidf_(v1);
                const uint32_t cg = pack2h(c, g);
                reinterpret_cast<uint32_t*>(g_CG)[(size_t)(m0 + rl) * H_ + bn * 64 + hl] = cg;
                sCG[rl * SCG_STRIDE + hl] = cg;
            }
        }
    }
    __syncthreads();

    // ---- fused chunk reduce: tile = 4 chunks of 32 rows; one (chunk,h) per thread ----
    {
        const int h   = tid & 63;
        const int seg = tid >> 6;          // 0..3 chunk within tile
        float A = 1.f, S = 0.f;
        const int t0 = seg * 32;
        #pragma unroll 8
        for (int t = 0; t < 32; t++) {
            const __half2 cgh = *reinterpret_cast<const __half2*>(&sCG[(t0 + t) * SCG_STRIDE + h]);
            const float2 f = __half22float2(cgh);
            S = f.x * S + (1.f - f.x) * f.y;
            A *= f.x;
        }
        const int b   = bm >> 5;                 // 32 bm tiles per batch
        const int chg = ((bm & 31) << 2) | seg;  // global chunk 0..127
        const int hg  = bn * 64 + h;
        g_A[(b * NC + chg) * H_ + hg] = A;
        g_S[(b * NC + chg) * H_ + hg] = S;
    }
}

// ----------------------------- scan phase B: warp-parallel chunk combine ----------------------
__global__ __launch_bounds__(256) void scan_phaseB(const float* __restrict__ h0)
{
    const int q    = blockIdx.x * 8 + (threadIdx.x >> 5);   // 0..1023
    const int lane = threadIdx.x & 31;
    const int b  = q >> 7;
    const int h4 = q & 127;

    const float4* A4 = reinterpret_cast<const float4*>(g_A);
    const float4* S4 = reinterpret_cast<const float4*>(g_S);
    float4* Hb4 = reinterpret_cast<float4*>(g_Hb);

    const int ob = (b * NC + 4 * lane) * 128 + h4;
    float4 Ai[4], Si[4];
    #pragma unroll
    for (int i = 0; i < 4; i++) {
        Ai[i] = A4[ob + i * 128];
        Si[i] = S4[ob + i * 128];
    }

    float4 Ap = Ai[0], Sp = Si[0];
    #pragma unroll
    for (int i = 1; i < 4; i++) {
        Sp.x = Ai[i].x*Sp.x + Si[i].x;  Ap.x *= Ai[i].x;
        Sp.y = Ai[i].y*Sp.y + Si[i].y;  Ap.y *= Ai[i].y;
        Sp.z = Ai[i].z*Sp.z + Si[i].z;  Ap.z *= Ai[i].z;
        Sp.w = Ai[i].w*Sp.w + Si[i].w;  Ap.w *= Ai[i].w;
    }

    #pragma unroll
    for (int d = 1; d < 32; d <<= 1) {
        float4 Au, Su;
        Au.x = __shfl_up_sync(0xFFFFFFFFu, Ap.x, d);
        Au.y = __shfl_up_sync(0xFFFFFFFFu, Ap.y, d);
        Au.z = __shfl_up_sync(0xFFFFFFFFu, Ap.z, d);
        Au.w = __shfl_up_sync(0xFFFFFFFFu, Ap.w, d);
        Su.x = __shfl_up_sync(0xFFFFFFFFu, Sp.x, d);
        Su.y = __shfl_up_sync(0xFFFFFFFFu, Sp.y, d);
        Su.z = __shfl_up_sync(0xFFFFFFFFu, Sp.z, d);
        Su.w = __shfl_up_sync(0xFFFFFFFFu, Sp.w, d);
        if (lane >= d) {
            Sp.x = Ap.x*Su.x + Sp.x;  Ap.x *= Au.x;
            Sp.y = Ap.y*Su.y + Sp.y;  Ap.y *= Au.y;
            Sp.z = Ap.z*Su.z + Sp.z;  Ap.z *= Au.z;
            Sp.w = Ap.w*Su.w + Sp.w;  Ap.w *= Au.w;
        }
    }

    float4 Ae, Se;
    Ae.x = __shfl_up_sync(0xFFFFFFFFu, Ap.x, 1);
    Ae.y = __shfl_up_sync(0xFFFFFFFFu, Ap.y, 1);
    Ae.z = __shfl_up_sync(0xFFFFFFFFu, Ap.z, 1);
    Ae.w = __shfl_up_sync(0xFFFFFFFFu, Ap.w, 1);
    Se.x = __shfl_up_sync(0xFFFFFFFFu, Sp.x, 1);
    Se.y = __shfl_up_sync(0xFFFFFFFFu, Sp.y, 1);
    Se.z = __shfl_up_sync(0xFFFFFFFFu, Sp.z, 1);
    Se.w = __shfl_up_sync(0xFFFFFFFFu, Sp.w, 1);
    if (lane == 0) {
        Ae = make_float4(1.f,1.f,1.f,1.f);
        Se = make_float4(0.f,0.f,0.f,0.f);
    }

    const float4 v = reinterpret_cast<const float4*>(h0)[b * 128 + h4];
    float4 st;
    st.x = (v.x >= 0.f) ? (v.x + 0.5f) : sigmoidf_(v.x);
    st.y = (v.y >= 0.f) ? (v.y + 0.5f) : sigmoidf_(v.y);
    st.z = (v.z >= 0.f) ? (v.z + 0.5f) : sigmoidf_(v.z);
    st.w = (v.w >= 0.f) ? (v.w + 0.5f) : sigmoidf_(v.w);

    st.x = Ae.x*st.x + Se.x;
    st.y = Ae.y*st.y + Se.y;
    st.z = Ae.z*st.z + Se.z;
    st.w = Ae.w*st.w + Se.w;

    #pragma unroll
    for (int i = 0; i < 4; i++) {
        Hb4[ob + i * 128] = st;
        st.x = Ai[i].x*st.x + Si[i].x;
        st.y = Ai[i].y*st.y + Si[i].y;
        st.z = Ai[i].z*st.z + Si[i].z;
        st.w = Ai[i].w*st.w + Si[i].w;
    }
}

// ----------------------------- scan phase C: rescan + output -----------------------------
__global__ __launch_bounds__(256) void scan_phaseC(float* __restrict__ out)
{
    const int idx = blockIdx.x * 256 + threadIdx.x;     // 0 .. 131071
    const int h4 = idx & 127;
    const int ch = (idx >> 7) & (NC - 1);
    const int b  = idx >> 14;
    const uint4* CG4 = reinterpret_cast<const uint4*>(g_CG);
    float4* O4 = reinterpret_cast<float4*>(out);
    size_t p = ((size_t)(b * T_ + ch * LC) * H_) / 4 + h4;

    float4 st = reinterpret_cast<const float4*>(g_Hb)[(b * NC + ch) * 128 + h4];
    #pragma unroll 4
    for (int t = 0; t < LC; t++, p += H_/4) {
        const uint4 u = CG4[p];
        const float2 a0 = __half22float2(*reinterpret_cast<const __half2*>(&u.x));
        const float2 a1 = __half22float2(*reinterpret_cast<const __half2*>(&u.y));
        const float2 a2 = __half22float2(*reinterpret_cast<const __half2*>(&u.z));
        const float2 a3 = __half22float2(*reinterpret_cast<const __half2*>(&u.w));
        st.x = a0.x*st.x + (1.f-a0.x)*a0.y;
        st.y = a1.x*st.y + (1.f-a1.x)*a1.y;
        st.z = a2.x*st.z + (1.f-a2.x)*a2.y;
        st.w = a3.x*st.w + (1.f-a3.x)*a3.y;
        O4[p] = st;
    }
}

extern "C" void kernel_launch(void* const* d_in, const int* in_sizes, int n_in,
                              void* d_out, int out_size)
{
    const float* x  = (const float*)d_in[0];
    const float* h0 = (const float*)d_in[1];
    const float* Wz = (const float*)d_in[2];
    const float* bz = (const float*)d_in[3];
    const float* Wh = (const float*)d_in[4];
    const float* bh = (const float*)d_in[5];
    float* out = (float*)d_out;

    cudaFuncSetAttribute(gemm_act_kernel, cudaFuncAttributeMaxDynamicSharedMemorySize, GEMM_SMEM);

    prep_kernel<<<(XBLOCKS + WPAIRS) / 8, 256>>>(x, Wz, Wh);
    gemm_act_kernel<<<dim3(8, 256), 256, GEMM_SMEM>>>(bz, bh);
    scan_phaseB<<<128, 256>>>(h0);
    scan_phaseC<<<512, 256>>>(out);
}